// round 13
// baseline (speedup 1.0000x reference)
#include <cuda_runtime.h>
#include <cuda_fp16.h>
#include <cstdint>
#include <cstddef>

// ============================================================================
// Problem constants
// ============================================================================
constexpr int SEQ = 2048, HID = 2048, HEADS = 16, HD = 128, BATCH = 2;
constexpr int TILEB  = 128 * 80;          // 128x32-fp16 tile, 80B padded rows
constexpr int STAGEB = 2 * TILEB;         // A, B tiles
constexpr int SMEM_BYTES = 67584;         // max(2*STAGEB=40960, transpose 128*132*4)

// ============================================================================
// Device scratch pool (all fp16)
// ============================================================================
constexpr size_t MB = 1048576ull;
constexpr size_t OFF_XH  = 0;
constexpr size_t OFF_WQH = 16*MB;
constexpr size_t OFF_WKH = 24*MB;
constexpr size_t OFF_WVH = 32*MB;
constexpr size_t OFF_WOH = 40*MB;
constexpr size_t OFF_QH  = 48*MB;      // Q fp16 (scale*log2e folded in)
constexpr size_t OFF_KH  = 64*MB;
constexpr size_t OFF_VTH = 80*MB;      // V^T fp16
constexpr size_t OFF_AH  = 96*MB;      // attn fp16
constexpr size_t POOL_SZ = 112*MB;

__device__ __align__(1024) unsigned char g_pool[POOL_SZ];

// ============================================================================
// Helpers
// ============================================================================
__device__ __forceinline__ uint32_t smem_u32(const void* p) {
    uint32_t a;
    asm("{ .reg .u64 t; cvta.to.shared.u64 t, %1; cvt.u32.u64 %0, t; }"
        : "=r"(a) : "l"(p));
    return a;
}
__device__ __forceinline__ void cp_async16(uint32_t dst, const void* src) {
    asm volatile("cp.async.cg.shared.global [%0], [%1], 16;"
                 :: "r"(dst), "l"(src) : "memory");
}
#define CP_COMMIT() asm volatile("cp.async.commit_group;" ::: "memory")
#define CP_WAIT(n)  asm volatile("cp.async.wait_group %0;" :: "n"(n) : "memory")

__device__ __forceinline__ void ldsm4(uint32_t r[4], uint32_t a) {
    asm volatile("ldmatrix.sync.aligned.m8n8.x4.shared.b16 {%0,%1,%2,%3}, [%4];"
                 : "=r"(r[0]), "=r"(r[1]), "=r"(r[2]), "=r"(r[3]) : "r"(a));
}
__device__ __forceinline__ void mma16816(float c[4], const uint32_t a[4],
                                         const uint32_t b0, const uint32_t b1) {
    asm volatile(
        "mma.sync.aligned.m16n8k16.row.col.f32.f16.f16.f32 "
        "{%0,%1,%2,%3}, {%4,%5,%6,%7}, {%8,%9}, {%0,%1,%2,%3};"
        : "+f"(c[0]), "+f"(c[1]), "+f"(c[2]), "+f"(c[3])
        : "r"(a[0]), "r"(a[1]), "r"(a[2]), "r"(a[3]), "r"(b0), "r"(b1));
}
__device__ __forceinline__ uint32_t hf2pack(float a, float b) {
    __half2 t;
    t.x = __float2half_rn(a);
    t.y = __float2half_rn(b);
    return *reinterpret_cast<uint32_t*>(&t);
}
__device__ __forceinline__ uint32_t cvt_f16x2(float lo, float hi) {
    uint32_t d;
    asm("cvt.rn.f16x2.f32 %0, %1, %2;" : "=r"(d) : "f"(hi), "f"(lo));
    return d;
}
__device__ __forceinline__ uint32_t ex2_f16x2(uint32_t s) {
    uint32_t d;
    asm("ex2.approx.f16x2 %0, %1;" : "=r"(d) : "r"(s));
    return d;
}
__device__ __forceinline__ float sum_f16x2(uint32_t p) {
    __half2 h = *reinterpret_cast<__half2*>(&p);
    float2 f = __half22float2(h);
    return f.x + f.y;
}
__device__ __forceinline__ uint32_t swz(uint32_t o) { return o ^ ((o >> 3) & 0x70); }

// ============================================================================
// fp16 GEMM mainloop (unchanged): acc = A @ B^T, 128x128, BK=32.
// ============================================================================
__device__ __forceinline__ void mma_mainloop(
    uint32_t sb, const __half* pAh, const __half* pBh,
    int lda, int ldb, int K, int tid, float acc[2][8][4])
{
    const int lane = tid & 31, wid = tid >> 5;
    const int wm = wid & 3, wn = wid >> 2;
    const int frow = tid >> 2, fch = tid & 3;
    const uint32_t fdst = (uint32_t)frow * 80 + (uint32_t)fch * 16;

    #define FILL_TILE(dstBase, g, ld) do {                                      \
        const char* _g = (const char*)(g) + ((size_t)_k0 + fch * 8) * 2;        \
        cp_async16((dstBase) + fdst, _g + (size_t)frow * (ld) * 2);             \
        cp_async16((dstBase) + fdst + 64 * 80, _g + (size_t)(frow + 64) * (ld) * 2); \
    } while (0)

    #define FILL_STAGE(IT) do {                                                 \
        const uint32_t _st = sb + (uint32_t)((IT) & 1) * STAGEB;                \
        const int _k0 = (IT) * 32;                                              \
        FILL_TILE(_st, pAh, lda);                                               \
        FILL_TILE(_st + TILEB, pBh, ldb);                                       \
        CP_COMMIT();                                                            \
    } while (0)

    const uint32_t aOff = (uint32_t)(wm * 32 + (lane & 15)) * 80
                        + (uint32_t)((lane >> 4) & 1) * 16;
    const int nl = (lane & 7) + ((lane >> 4) & 1) * 8;
    const int kh = (lane >> 3) & 1;
    const uint32_t bOff = (uint32_t)(wn * 64 + nl) * 80 + (uint32_t)kh * 16;

    const int NIT = K >> 5;
    FILL_STAGE(0);

    for (int it = 0; it < NIT; ++it) {
        if (it + 1 < NIT) { FILL_STAGE(it + 1); CP_WAIT(1); }
        else              { CP_WAIT(0); }
        __syncthreads();
        const uint32_t st = sb + (uint32_t)(it & 1) * STAGEB;
        #pragma unroll
        for (int ks = 0; ks < 2; ks++) {
            uint32_t th[2][4];
            ldsm4(th[0], st + TILEB + bOff + ks * 32);
            uint32_t ahf[2][4];
            #pragma unroll
            for (int mf = 0; mf < 2; mf++)
                ldsm4(ahf[mf], st + aOff + mf * (16 * 80) + ks * 32);
            #pragma unroll
            for (int nq = 0; nq < 4; nq++) {
                const int cur = nq & 1;
                if (nq < 3) {
                    ldsm4(th[cur ^ 1],
                          st + TILEB + bOff + (nq + 1) * (16 * 80) + ks * 32);
                }
                #pragma unroll
                for (int mf = 0; mf < 2; mf++) {
                    mma16816(acc[mf][2 * nq],     ahf[mf], th[cur][0], th[cur][1]);
                    mma16816(acc[mf][2 * nq + 1], ahf[mf], th[cur][2], th[cur][3]);
                }
            }
        }
        __syncthreads();
    }
    #undef FILL_STAGE
    #undef FILL_TILE
}

// ============================================================================
// Fused QKV projection (unchanged, scale includes log2e)
// ============================================================================
__global__ void __launch_bounds__(256, 2)
qkv_mma(const __half* __restrict__ Xh,
        const __half* __restrict__ Wqh, const __half* __restrict__ Wkh,
        const __half* __restrict__ Wvh,
        const float* __restrict__ bq, const float* __restrict__ bk,
        const float* __restrict__ bv,
        __half* __restrict__ Qh, __half* __restrict__ Kh,
        __half* __restrict__ VTh, float scale)
{
    extern __shared__ __align__(128) unsigned char smem[];
    const uint32_t sb = smem_u32(smem);
    const int tid = threadIdx.x, lane = tid & 31, wid = tid >> 5;
    const int wm = wid & 3, wn = wid >> 2;
    const int bx = blockIdx.x, by = blockIdx.y, bz = blockIdx.z;

    const __half* Bh = (bz == 0) ? Wqh : (bz == 1) ? Wkh : Wvh;
    const float* bias = (bz == 0) ? bq : (bz == 1) ? bk : bv;
    const float alpha = (bz == 0) ? scale : 1.0f;

    const __half* pAh = Xh + (size_t)by * 128 * HID;
    const __half* pBh = Bh + (size_t)bx * 128 * HID;

    float acc[2][8][4];
    #pragma unroll
    for (int i = 0; i < 2; i++)
        #pragma unroll
        for (int j = 0; j < 8; j++)
            #pragma unroll
            for (int q = 0; q < 4; q++) acc[i][j][q] = 0.0f;

    mma_mainloop(sb, pAh, pBh, HID, HID, HID, tid, acc);

    const int mrow0 = wm * 32 + (lane >> 2);
    const int ncol0 = wn * 64 + (lane & 3) * 2;

    if (bz == 2) {
        float* tb = (float*)smem;  // [128][132]
        #pragma unroll
        for (int mf = 0; mf < 2; mf++)
            #pragma unroll
            for (int nf = 0; nf < 8; nf++) {
                const int r = mrow0 + mf * 16;
                const int c = ncol0 + nf * 8;
                tb[r * 132 + c]           = acc[mf][nf][0];
                tb[r * 132 + c + 1]       = acc[mf][nf][1];
                tb[(r + 8) * 132 + c]     = acc[mf][nf][2];
                tb[(r + 8) * 132 + c + 1] = acc[mf][nf][3];
            }
        __syncthreads();
        const int d = tid & 127, sh = tid >> 7;
        const float bvv = bias[bx * 128 + d];
        const int b = by >> 4;
        const size_t base = (((size_t)(b * HEADS + bx)) * HD + d) * SEQ
                          + (size_t)(by & 15) * 128 + sh * 64;
        #pragma unroll 8
        for (int s = 0; s < 64; s += 2) {
            float v0 = tb[(sh * 64 + s) * 132 + d] + bvv;
            float v1 = tb[(sh * 64 + s + 1) * 132 + d] + bvv;
            *(uint32_t*)(VTh + base + s) = hf2pack(v0, v1);
        }
        return;
    }

    __half* Ch = (bz == 0) ? Qh : Kh;
    #pragma unroll
    for (int mf = 0; mf < 2; mf++)
        #pragma unroll
        for (int nf = 0; nf < 8; nf++) {
            const int r = by * 128 + mrow0 + mf * 16;
            const int c = ncol0 + nf * 8;
            const float* a = acc[mf][nf];
            const int b = r >> 11, s = r & 2047;
            const float b0 = bias[bx * 128 + c], b1 = bias[bx * 128 + c + 1];
            const size_t base = (((size_t)(b * HEADS + bx)) * SEQ + s) * HD + c;
            *(uint32_t*)(Ch + base) =
                hf2pack((a[0] + b0) * alpha, (a[1] + b1) * alpha);
            *(uint32_t*)(Ch + base + (size_t)8 * HD) =
                hf2pack((a[2] + b0) * alpha, (a[3] + b1) * alpha);
        }
}

// ============================================================================
// Output projection GEMM (unchanged)
// ============================================================================
__global__ void __launch_bounds__(256, 2)
gemm_out(const __half* __restrict__ Ah, const __half* __restrict__ Bh,
         float* __restrict__ Cf, const float* __restrict__ bias)
{
    extern __shared__ __align__(128) unsigned char smem[];
    const uint32_t sb = smem_u32(smem);
    const int tid = threadIdx.x, lane = tid & 31, wid = tid >> 5;
    const int wm = wid & 3, wn = wid >> 2;
    const int bx = blockIdx.x, by = blockIdx.y;

    const __half* pAh = Ah + (size_t)by * 128 * HID;
    const __half* pBh = Bh + (size_t)bx * 128 * HID;

    float acc[2][8][4];
    #pragma unroll
    for (int i = 0; i < 2; i++)
        #pragma unroll
        for (int j = 0; j < 8; j++)
            #pragma unroll
            for (int q = 0; q < 4; q++) acc[i][j][q] = 0.0f;

    mma_mainloop(sb, pAh, pBh, HID, HID, HID, tid, acc);

    const int mrow0 = wm * 32 + (lane >> 2);
    const int ncol0 = wn * 64 + (lane & 3) * 2;
    #pragma unroll
    for (int mf = 0; mf < 2; mf++)
        #pragma unroll
        for (int nf = 0; nf < 8; nf++) {
            const int r = by * 128 + mrow0 + mf * 16;
            const int c = ncol0 + nf * 8;
            const float* a = acc[mf][nf];
            const float b0 = bias[bx * 128 + c], b1 = bias[bx * 128 + c + 1];
            float* p0 = Cf + (size_t)r * HID + (size_t)bx * 128 + c;
            float2 w0; w0.x = a[0] + b0; w0.y = a[1] + b1;
            float2 w1; w1.x = a[2] + b0; w1.y = a[3] + b1;
            *(float2*)p0 = w0;
            *(float2*)(p0 + (size_t)8 * HID) = w1;
        }
}

// ============================================================================
// Fused flash attention, register-resident P, 128 threads / 64 q-rows per CTA
// -> 2 CTAs/SM. Each warp: 16 q-rows x all 64 kv. Quad-local softmax.
// smem: Q 0..16K (2 panels of 8K), KV buf b @ 16K + b*32K: K p0 8K, K p1 8K, V 16K
// ============================================================================
constexpr int FL_KV0  = 16384;
constexpr int FL_SMEM = 81920;

__global__ void __launch_bounds__(128, 2)
flash_attn(const __half* __restrict__ Qh_, const __half* __restrict__ Kh_,
           const __half* __restrict__ Vh_, __half* __restrict__ Ah_)
{
    extern __shared__ __align__(128) unsigned char smem[];
    const uint32_t sb = smem_u32(smem);
    const int tid = threadIdx.x, lane = tid & 31, wid = tid >> 5;
    const int qt = blockIdx.x, bh = blockIdx.y;

    const size_t qoff = ((size_t)bh * SEQ + (size_t)qt * 64) * HD;
    const size_t koff = (size_t)bh * SEQ * HD;
    const size_t voff = (size_t)bh * HD * SEQ;

    {   // Q tile: 64 rows x 128 d (2 panels of 64 d, 8K each)
        const int r = tid >> 1;
        const size_t gq = qoff + (size_t)r * HD;
        #pragma unroll
        for (int j = 0; j < 4; j++) {
            const uint32_t cb = (uint32_t)(tid & 1) * 64 + j * 16;
            const uint32_t off = swz((uint32_t)r * 128 + cb);
            cp_async16(sb + off,        (const char*)(Qh_ + gq)      + cb);
            cp_async16(sb + 8192 + off, (const char*)(Qh_ + gq + 64) + cb);
        }
    }

    auto fill_kv = [&](int it) {
        const uint32_t bufb = sb + FL_KV0 + (uint32_t)(it & 1) * 32768;
        {   // K: 64 rows x 128 d (2 panels of 8K)
            const int r = tid >> 1;
            const size_t gk = koff + ((size_t)it * 64 + r) * HD;
            #pragma unroll
            for (int j = 0; j < 4; j++) {
                const uint32_t cb = (uint32_t)(tid & 1) * 64 + j * 16;
                const uint32_t off = swz((uint32_t)r * 128 + cb);
                cp_async16(bufb + off,        (const char*)(Kh_ + gk)      + cb);
                cp_async16(bufb + 8192 + off, (const char*)(Kh_ + gk + 64) + cb);
            }
        }
        {   // V^T: 128 d-rows x 64 kv (16K)
            const int r = tid;
            const size_t gv = voff + (size_t)r * SEQ + (size_t)it * 64;
            #pragma unroll
            for (int j = 0; j < 8; j++) {
                const uint32_t cb = (uint32_t)j * 16;
                const uint32_t off = swz((uint32_t)r * 128 + cb);
                cp_async16(bufb + 16384 + off, (const char*)(Vh_ + gv) + cb);
            }
        }
        CP_COMMIT();
    };

    fill_kv(0);

    const int nl = (lane & 7) + ((lane >> 4) & 1) * 8;
    const int kh = (lane >> 3) & 1;
    const uint32_t arow = (uint32_t)(wid * 16 + (lane & 15));
    const uint32_t acol16 = (uint32_t)(((lane >> 4) & 1) * 16);

    float O[16][4];
    #pragma unroll
    for (int j = 0; j < 16; j++)
        #pragma unroll
        for (int q = 0; q < 4; q++) O[j][q] = 0.0f;
    float mrun[2] = {-1e30f, -1e30f}, lrun[2] = {0.0f, 0.0f};

    for (int it = 0; it < SEQ / 64; ++it) {
        CP_WAIT(0);
        __syncthreads();
        if (it + 1 < SEQ / 64) fill_kv(it + 1);
        const uint32_t kb = sb + FL_KV0 + (uint32_t)(it & 1) * 32768;

        // ---- S (log2 domain) = Qs K^T : warp computes 16 q x 64 kv ----
        float S[8][4];
        #pragma unroll
        for (int nf = 0; nf < 8; nf++)
            #pragma unroll
            for (int q = 0; q < 4; q++) S[nf][q] = 0.0f;

        #pragma unroll
        for (int ks = 0; ks < 8; ++ks) {
            const uint32_t qp = sb + (uint32_t)(ks >> 2) * 8192;
            const uint32_t kp = kb + (uint32_t)(ks >> 2) * 8192;
            const uint32_t ac = acol16 + (uint32_t)(ks & 3) * 32;
            uint32_t qh[4];
            ldsm4(qh, qp + swz(arow * 128 + ac));
            uint32_t bh2[8][2];
            #pragma unroll
            for (int g = 0; g < 4; g++) {
                const uint32_t ro = (uint32_t)(nl + g * 16) * 128
                                  + kh * 16 + (ks & 3) * 32;
                uint32_t t[4];
                ldsm4(t, kp + swz(ro));
                bh2[2*g][0] = t[0]; bh2[2*g][1] = t[1];
                bh2[2*g+1][0] = t[2]; bh2[2*g+1][1] = t[3];
            }
            #pragma unroll
            for (int nf = 0; nf < 8; nf++)
                mma16816(S[nf], qh, bh2[nf][0], bh2[nf][1]);
        }

        // ---- online softmax: quad-local only ----
        float mx0 = -1e30f, mx1 = -1e30f;
        #pragma unroll
        for (int nf = 0; nf < 8; nf++) {
            mx0 = fmaxf(mx0, fmaxf(S[nf][0], S[nf][1]));
            mx1 = fmaxf(mx1, fmaxf(S[nf][2], S[nf][3]));
        }
        mx0 = fmaxf(mx0, __shfl_xor_sync(0xffffffffu, mx0, 1));
        mx0 = fmaxf(mx0, __shfl_xor_sync(0xffffffffu, mx0, 2));
        mx1 = fmaxf(mx1, __shfl_xor_sync(0xffffffffu, mx1, 1));
        mx1 = fmaxf(mx1, __shfl_xor_sync(0xffffffffu, mx1, 2));
        const float mn0 = fmaxf(mrun[0], mx0);
        const float mn1 = fmaxf(mrun[1], mx1);
        const float fac0 = exp2f(mrun[0] - mn0);
        const float fac1 = exp2f(mrun[1] - mn1);
        mrun[0] = mn0; mrun[1] = mn1;

        uint32_t P[4][4];
        float rs0 = 0.0f, rs1 = 0.0f;
        #pragma unroll
        for (int ks = 0; ks < 4; ++ks) {
            #pragma unroll
            for (int j = 0; j < 2; j++) {
                const int nf = 2 * ks + j;
                const uint32_t p0 = ex2_f16x2(cvt_f16x2(S[nf][0] - mn0, S[nf][1] - mn0));
                const uint32_t p1 = ex2_f16x2(cvt_f16x2(S[nf][2] - mn1, S[nf][3] - mn1));
                P[ks][2 * j]     = p0;
                P[ks][2 * j + 1] = p1;
                rs0 += sum_f16x2(p0);
                rs1 += sum_f16x2(p1);
            }
        }
        rs0 += __shfl_xor_sync(0xffffffffu, rs0, 1);
        rs0 += __shfl_xor_sync(0xffffffffu, rs0, 2);
        rs1 += __shfl_xor_sync(0xffffffffu, rs1, 1);
        rs1 += __shfl_xor_sync(0xffffffffu, rs1, 2);
        lrun[0] = lrun[0] * fac0 + rs0;
        lrun[1] = lrun[1] * fac1 + rs1;

        #pragma unroll
        for (int nf = 0; nf < 16; nf++) {
            O[nf][0] *= fac0; O[nf][1] *= fac0;
            O[nf][2] *= fac1; O[nf][3] *= fac1;
        }

        // ---- O += P V : P in registers, V from smem ----
        #pragma unroll
        for (int ks = 0; ks < 4; ++ks) {
            uint32_t vh2[16][2];
            #pragma unroll
            for (int g = 0; g < 8; g++) {
                const uint32_t ro = (uint32_t)(nl + g * 16) * 128
                                  + kh * 16 + ks * 32;
                uint32_t t[4];
                ldsm4(t, kb + 16384 + swz(ro));
                vh2[2*g][0] = t[0]; vh2[2*g][1] = t[1];
                vh2[2*g+1][0] = t[2]; vh2[2*g+1][1] = t[3];
            }
            #pragma unroll
            for (int nf = 0; nf < 16; nf++)
                mma16816(O[nf], P[ks], vh2[nf][0], vh2[nf][1]);
        }
    }

    // ---- normalize and write ----
    const float linv0 = 1.0f / lrun[0];
    const float linv1 = 1.0f / lrun[1];
    const int b = bh >> 4, h = bh & 15;
    const int r = qt * 64 + wid * 16 + (lane >> 2);
    #pragma unroll
    for (int nf = 0; nf < 16; nf++) {
        const int c = nf * 8 + (lane & 3) * 2;
        const size_t base = ((size_t)b * SEQ + r) * HID + (size_t)h * 128 + c;
        *(uint32_t*)(Ah_ + base) = hf2pack(O[nf][0] * linv0, O[nf][1] * linv0);
        *(uint32_t*)(Ah_ + base + (size_t)8 * HID) =
            hf2pack(O[nf][2] * linv1, O[nf][3] * linv1);
    }
}

// ============================================================================
// Conversions
// ============================================================================
__global__ __launch_bounds__(256)
void conv_round_h(const float4* __restrict__ in, uint32_t* __restrict__ hi, int n4)
{
    int i = blockIdx.x * blockDim.x + threadIdx.x;
    if (i >= n4) return;
    float4 v = in[i];
    hi[2 * i]     = hf2pack(v.x, v.y);
    hi[2 * i + 1] = hf2pack(v.z, v.w);
}

__global__ __launch_bounds__(256)
void conv_round_h4(const float4* __restrict__ w0, const float4* __restrict__ w1,
                   const float4* __restrict__ w2, const float4* __restrict__ w3,
                   uint32_t* __restrict__ o0, uint32_t* __restrict__ o1,
                   uint32_t* __restrict__ o2, uint32_t* __restrict__ o3, int n4)
{
    int i = blockIdx.x * blockDim.x + threadIdx.x;
    if (i >= n4) return;
    const float4* in = (blockIdx.y == 0) ? w0 : (blockIdx.y == 1) ? w1
                     : (blockIdx.y == 2) ? w2 : w3;
    uint32_t* hi = (blockIdx.y == 0) ? o0 : (blockIdx.y == 1) ? o1
                 : (blockIdx.y == 2) ? o2 : o3;
    float4 v = in[i];
    hi[2 * i]     = hf2pack(v.x, v.y);
    hi[2 * i + 1] = hf2pack(v.z, v.w);
}

// ============================================================================
// kernel_launch
// ============================================================================
extern "C" void kernel_launch(void* const* d_in, const int* in_sizes, int n_in,
                              void* d_out, int out_size)
{
    const float* x  = (const float*)d_in[0];
    const float* Wq = (const float*)d_in[1];
    const float* bq = (const float*)d_in[2];
    const float* Wk = (const float*)d_in[3];
    const float* bk = (const float*)d_in[4];
    const float* Wv = (const float*)d_in[5];
    const float* bv = (const float*)d_in[6];
    const float* Wo = (const float*)d_in[7];
    const float* bo = (const float*)d_in[8];
    float* out = (float*)d_out;

    unsigned char* pool;
    cudaGetSymbolAddress((void**)&pool, g_pool);
    auto hfp = [&](size_t off) { return (__half*)(pool + off); };
    auto u32 = [&](size_t off) { return (uint32_t*)(pool + off); };

    cudaFuncSetAttribute(qkv_mma,    cudaFuncAttributeMaxDynamicSharedMemorySize, SMEM_BYTES);
    cudaFuncSetAttribute(gemm_out,   cudaFuncAttributeMaxDynamicSharedMemorySize, SMEM_BYTES);
    cudaFuncSetAttribute(flash_attn, cudaFuncAttributeMaxDynamicSharedMemorySize, FL_SMEM);

    // 1/sqrt(128) * log2(e): scores come out in log2 domain
    const float scale = 0.08838834764831845f * 1.44269504088896340736f;

    // 1) conversions
    conv_round_h<<<8192, 256>>>((const float4*)x, u32(OFF_XH), 2097152);
    dim3 gW(4096, 4, 1);
    conv_round_h4<<<gW, 256>>>((const float4*)Wq, (const float4*)Wk,
                               (const float4*)Wv, (const float4*)Wo,
                               u32(OFF_WQH), u32(OFF_WKH),
                               u32(OFF_WVH), u32(OFF_WOH), 1048576);

    // 2) fused QKV projections
    dim3 gQKV(16, 32, 3);
    qkv_mma<<<gQKV, 256, SMEM_BYTES>>>(
        hfp(OFF_XH),
        hfp(OFF_WQH), hfp(OFF_WKH), hfp(OFF_WVH),
        bq, bk, bv,
        hfp(OFF_QH), hfp(OFF_KH), hfp(OFF_VTH), scale);

    // 3) fused flash attention (64 q-rows/CTA, 2 CTAs/SM)
    dim3 gF(SEQ / 64, BATCH * HEADS, 1);
    flash_attn<<<gF, 128, FL_SMEM>>>(hfp(OFF_QH), hfp(OFF_KH),
                                     hfp(OFF_VTH), hfp(OFF_AH));

    // 4) output projection
    dim3 gO(16, 32, 1);
    gemm_out<<<gO, 256, SMEM_BYTES>>>(hfp(OFF_AH), hfp(OFF_WOH), out, bo);
}

// round 14
// speedup vs baseline: 1.0545x; 1.0545x over previous
#include <cuda_runtime.h>
#include <cuda_fp16.h>
#include <cstdint>
#include <cstddef>

// ============================================================================
// Problem constants
// ============================================================================
constexpr int SEQ = 2048, HID = 2048, HEADS = 16, HD = 128, BATCH = 2;
constexpr int TILEB  = 128 * 80;          // 128x32-fp16 tile, 80B padded rows
constexpr int STAGEB = 2 * TILEB;         // A, B tiles (20 KB)
constexpr int SMEM_BYTES = 67584;         // max(3*STAGEB=61440, transpose 128*132*4)

// ============================================================================
// Device scratch pool (all fp16)
// ============================================================================
constexpr size_t MB = 1048576ull;
constexpr size_t OFF_XH  = 0;
constexpr size_t OFF_WQH = 16*MB;
constexpr size_t OFF_WKH = 24*MB;
constexpr size_t OFF_WVH = 32*MB;
constexpr size_t OFF_WOH = 40*MB;
constexpr size_t OFF_QH  = 48*MB;      // Q fp16 (scale*log2e folded in)
constexpr size_t OFF_KH  = 64*MB;
constexpr size_t OFF_VTH = 80*MB;      // V^T fp16
constexpr size_t OFF_AH  = 96*MB;      // attn fp16
constexpr size_t POOL_SZ = 112*MB;

__device__ __align__(1024) unsigned char g_pool[POOL_SZ];

// ============================================================================
// Helpers
// ============================================================================
__device__ __forceinline__ uint32_t smem_u32(const void* p) {
    uint32_t a;
    asm("{ .reg .u64 t; cvta.to.shared.u64 t, %1; cvt.u32.u64 %0, t; }"
        : "=r"(a) : "l"(p));
    return a;
}
__device__ __forceinline__ void cp_async16(uint32_t dst, const void* src) {
    asm volatile("cp.async.cg.shared.global [%0], [%1], 16;"
                 :: "r"(dst), "l"(src) : "memory");
}
#define CP_COMMIT() asm volatile("cp.async.commit_group;" ::: "memory")
#define CP_WAIT(n)  asm volatile("cp.async.wait_group %0;" :: "n"(n) : "memory")

__device__ __forceinline__ void ldsm4(uint32_t r[4], uint32_t a) {
    asm volatile("ldmatrix.sync.aligned.m8n8.x4.shared.b16 {%0,%1,%2,%3}, [%4];"
                 : "=r"(r[0]), "=r"(r[1]), "=r"(r[2]), "=r"(r[3]) : "r"(a));
}
__device__ __forceinline__ void mma16816(float c[4], const uint32_t a[4],
                                         const uint32_t b0, const uint32_t b1) {
    asm volatile(
        "mma.sync.aligned.m16n8k16.row.col.f32.f16.f16.f32 "
        "{%0,%1,%2,%3}, {%4,%5,%6,%7}, {%8,%9}, {%0,%1,%2,%3};"
        : "+f"(c[0]), "+f"(c[1]), "+f"(c[2]), "+f"(c[3])
        : "r"(a[0]), "r"(a[1]), "r"(a[2]), "r"(a[3]), "r"(b0), "r"(b1));
}
__device__ __forceinline__ uint32_t hf2pack(float a, float b) {
    __half2 t;
    t.x = __float2half_rn(a);
    t.y = __float2half_rn(b);
    return *reinterpret_cast<uint32_t*>(&t);
}
__device__ __forceinline__ uint32_t cvt_f16x2(float lo, float hi) {
    uint32_t d;
    asm("cvt.rn.f16x2.f32 %0, %1, %2;" : "=r"(d) : "f"(hi), "f"(lo));
    return d;
}
__device__ __forceinline__ uint32_t ex2_f16x2(uint32_t s) {
    uint32_t d;
    asm("ex2.approx.f16x2 %0, %1;" : "=r"(d) : "r"(s));
    return d;
}
__device__ __forceinline__ float sum_f16x2(uint32_t p) {
    __half2 h = *reinterpret_cast<__half2*>(&p);
    float2 f = __half22float2(h);
    return f.x + f.y;
}
__device__ __forceinline__ uint32_t swz(uint32_t o) { return o ^ ((o >> 3) & 0x70); }

// ============================================================================
// fp16 GEMM mainloop: acc = A @ B^T, 128x128, BK=32, 3-stage cp.async.
// ============================================================================
__device__ __forceinline__ void mma_mainloop(
    uint32_t sb, const __half* pAh, const __half* pBh,
    int lda, int ldb, int K, int tid, float acc[2][8][4])
{
    const int lane = tid & 31, wid = tid >> 5;
    const int wm = wid & 3, wn = wid >> 2;
    const int frow = tid >> 2, fch = tid & 3;
    const uint32_t fdst = (uint32_t)frow * 80 + (uint32_t)fch * 16;

    #define FILL_TILE(dstBase, g, ld) do {                                      \
        const char* _g = (const char*)(g) + ((size_t)_k0 + fch * 8) * 2;        \
        cp_async16((dstBase) + fdst, _g + (size_t)frow * (ld) * 2);             \
        cp_async16((dstBase) + fdst + 64 * 80, _g + (size_t)(frow + 64) * (ld) * 2); \
    } while (0)

    #define FILL_STAGE(IT) do {                                                 \
        const uint32_t _st = sb + (uint32_t)((IT) % 3) * STAGEB;                \
        const int _k0 = (IT) * 32;                                              \
        FILL_TILE(_st, pAh, lda);                                               \
        FILL_TILE(_st + TILEB, pBh, ldb);                                       \
        CP_COMMIT();                                                            \
    } while (0)

    const uint32_t aOff = (uint32_t)(wm * 32 + (lane & 15)) * 80
                        + (uint32_t)((lane >> 4) & 1) * 16;
    const int nl = (lane & 7) + ((lane >> 4) & 1) * 8;
    const int kh = (lane >> 3) & 1;
    const uint32_t bOff = (uint32_t)(wn * 64 + nl) * 80 + (uint32_t)kh * 16;

    const int NIT = K >> 5;
    FILL_STAGE(0);
    if (NIT > 1) FILL_STAGE(1);

    for (int it = 0; it < NIT; ++it) {
        if (it + 2 < NIT)      { FILL_STAGE(it + 2); CP_WAIT(2); }
        else if (it + 1 < NIT) { CP_WAIT(1); }
        else                   { CP_WAIT(0); }
        __syncthreads();
        const uint32_t st = sb + (uint32_t)(it % 3) * STAGEB;
        #pragma unroll
        for (int ks = 0; ks < 2; ks++) {
            uint32_t th[2][4];
            ldsm4(th[0], st + TILEB + bOff + ks * 32);
            uint32_t ahf[2][4];
            #pragma unroll
            for (int mf = 0; mf < 2; mf++)
                ldsm4(ahf[mf], st + aOff + mf * (16 * 80) + ks * 32);
            #pragma unroll
            for (int nq = 0; nq < 4; nq++) {
                const int cur = nq & 1;
                if (nq < 3) {
                    ldsm4(th[cur ^ 1],
                          st + TILEB + bOff + (nq + 1) * (16 * 80) + ks * 32);
                }
                #pragma unroll
                for (int mf = 0; mf < 2; mf++) {
                    mma16816(acc[mf][2 * nq],     ahf[mf], th[cur][0], th[cur][1]);
                    mma16816(acc[mf][2 * nq + 1], ahf[mf], th[cur][2], th[cur][3]);
                }
            }
        }
        __syncthreads();
    }
    #undef FILL_STAGE
    #undef FILL_TILE
}

// ============================================================================
// Fused QKV projection (scale includes log2e)
// ============================================================================
__global__ void __launch_bounds__(256, 2)
qkv_mma(const __half* __restrict__ Xh,
        const __half* __restrict__ Wqh, const __half* __restrict__ Wkh,
        const __half* __restrict__ Wvh,
        const float* __restrict__ bq, const float* __restrict__ bk,
        const float* __restrict__ bv,
        __half* __restrict__ Qh, __half* __restrict__ Kh,
        __half* __restrict__ VTh, float scale)
{
    extern __shared__ __align__(128) unsigned char smem[];
    const uint32_t sb = smem_u32(smem);
    const int tid = threadIdx.x, lane = tid & 31, wid = tid >> 5;
    const int wm = wid & 3, wn = wid >> 2;
    const int bx = blockIdx.x, by = blockIdx.y, bz = blockIdx.z;

    const __half* Bh = (bz == 0) ? Wqh : (bz == 1) ? Wkh : Wvh;
    const float* bias = (bz == 0) ? bq : (bz == 1) ? bk : bv;
    const float alpha = (bz == 0) ? scale : 1.0f;

    const __half* pAh = Xh + (size_t)by * 128 * HID;
    const __half* pBh = Bh + (size_t)bx * 128 * HID;

    float acc[2][8][4];
    #pragma unroll
    for (int i = 0; i < 2; i++)
        #pragma unroll
        for (int j = 0; j < 8; j++)
            #pragma unroll
            for (int q = 0; q < 4; q++) acc[i][j][q] = 0.0f;

    mma_mainloop(sb, pAh, pBh, HID, HID, HID, tid, acc);

    const int mrow0 = wm * 32 + (lane >> 2);
    const int ncol0 = wn * 64 + (lane & 3) * 2;

    if (bz == 2) {
        float* tb = (float*)smem;  // [128][132]
        #pragma unroll
        for (int mf = 0; mf < 2; mf++)
            #pragma unroll
            for (int nf = 0; nf < 8; nf++) {
                const int r = mrow0 + mf * 16;
                const int c = ncol0 + nf * 8;
                tb[r * 132 + c]           = acc[mf][nf][0];
                tb[r * 132 + c + 1]       = acc[mf][nf][1];
                tb[(r + 8) * 132 + c]     = acc[mf][nf][2];
                tb[(r + 8) * 132 + c + 1] = acc[mf][nf][3];
            }
        __syncthreads();
        const int d = tid & 127, sh = tid >> 7;
        const float bvv = bias[bx * 128 + d];
        const int b = by >> 4;
        const size_t base = (((size_t)(b * HEADS + bx)) * HD + d) * SEQ
                          + (size_t)(by & 15) * 128 + sh * 64;
        #pragma unroll 8
        for (int s = 0; s < 64; s += 2) {
            float v0 = tb[(sh * 64 + s) * 132 + d] + bvv;
            float v1 = tb[(sh * 64 + s + 1) * 132 + d] + bvv;
            *(uint32_t*)(VTh + base + s) = hf2pack(v0, v1);
        }
        return;
    }

    __half* Ch = (bz == 0) ? Qh : Kh;
    #pragma unroll
    for (int mf = 0; mf < 2; mf++)
        #pragma unroll
        for (int nf = 0; nf < 8; nf++) {
            const int r = by * 128 + mrow0 + mf * 16;
            const int c = ncol0 + nf * 8;
            const float* a = acc[mf][nf];
            const int b = r >> 11, s = r & 2047;
            const float b0 = bias[bx * 128 + c], b1 = bias[bx * 128 + c + 1];
            const size_t base = (((size_t)(b * HEADS + bx)) * SEQ + s) * HD + c;
            *(uint32_t*)(Ch + base) =
                hf2pack((a[0] + b0) * alpha, (a[1] + b1) * alpha);
            *(uint32_t*)(Ch + base + (size_t)8 * HD) =
                hf2pack((a[2] + b0) * alpha, (a[3] + b1) * alpha);
        }
}

// ============================================================================
// Output projection GEMM
// ============================================================================
__global__ void __launch_bounds__(256, 2)
gemm_out(const __half* __restrict__ Ah, const __half* __restrict__ Bh,
         float* __restrict__ Cf, const float* __restrict__ bias)
{
    extern __shared__ __align__(128) unsigned char smem[];
    const uint32_t sb = smem_u32(smem);
    const int tid = threadIdx.x, lane = tid & 31, wid = tid >> 5;
    const int wm = wid & 3, wn = wid >> 2;
    const int bx = blockIdx.x, by = blockIdx.y;

    const __half* pAh = Ah + (size_t)by * 128 * HID;
    const __half* pBh = Bh + (size_t)bx * 128 * HID;

    float acc[2][8][4];
    #pragma unroll
    for (int i = 0; i < 2; i++)
        #pragma unroll
        for (int j = 0; j < 8; j++)
            #pragma unroll
            for (int q = 0; q < 4; q++) acc[i][j][q] = 0.0f;

    mma_mainloop(sb, pAh, pBh, HID, HID, HID, tid, acc);

    const int mrow0 = wm * 32 + (lane >> 2);
    const int ncol0 = wn * 64 + (lane & 3) * 2;
    #pragma unroll
    for (int mf = 0; mf < 2; mf++)
        #pragma unroll
        for (int nf = 0; nf < 8; nf++) {
            const int r = by * 128 + mrow0 + mf * 16;
            const int c = ncol0 + nf * 8;
            const float* a = acc[mf][nf];
            const float b0 = bias[bx * 128 + c], b1 = bias[bx * 128 + c + 1];
            float* p0 = Cf + (size_t)r * HID + (size_t)bx * 128 + c;
            float2 w0; w0.x = a[0] + b0; w0.y = a[1] + b1;
            float2 w1; w1.x = a[2] + b0; w1.y = a[3] + b1;
            *(float2*)p0 = w0;
            *(float2*)(p0 + (size_t)8 * HID) = w1;
        }
}

// ============================================================================
// Fused flash attention — EXACT R12 version (proven 254 us):
// 256 threads, 128 q-rows/CTA, register-resident P, quad-local softmax.
// smem: Q 0..32K (2 panels), KV buf b @ 32K + b*32K: K p0 8K, K p1 8K, V 16K
// ============================================================================
constexpr int FL_KV0  = 32768;
constexpr int FL_SMEM = 98304;

__global__ void __launch_bounds__(256, 1)
flash_attn(const __half* __restrict__ Qh_, const __half* __restrict__ Kh_,
           const __half* __restrict__ Vh_, __half* __restrict__ Ah_)
{
    extern __shared__ __align__(128) unsigned char smem[];
    const uint32_t sb = smem_u32(smem);
    const int tid = threadIdx.x, lane = tid & 31, wid = tid >> 5;
    const int qt = blockIdx.x, bh = blockIdx.y;

    const size_t qoff = ((size_t)bh * SEQ + (size_t)qt * 128) * HD;
    const size_t koff = (size_t)bh * SEQ * HD;
    const size_t voff = (size_t)bh * HD * SEQ;

    {   // Q tile: 128 rows x 128 d (2 panels of 64 d)
        const int r = tid >> 1;
        const size_t gq = qoff + (size_t)r * HD;
        #pragma unroll
        for (int j = 0; j < 4; j++) {
            const uint32_t cb = (uint32_t)(tid & 1) * 64 + j * 16;
            const uint32_t off = swz((uint32_t)r * 128 + cb);
            cp_async16(sb + off,         (const char*)(Qh_ + gq)      + cb);
            cp_async16(sb + 16384 + off, (const char*)(Qh_ + gq + 64) + cb);
        }
    }

    auto fill_kv = [&](int it) {
        const uint32_t bufb = sb + FL_KV0 + (uint32_t)(it & 1) * 32768;
        {
            const int r = tid >> 2;
            const size_t gk = koff + ((size_t)it * 64 + r) * HD;
            #pragma unroll
            for (int j = 0; j < 2; j++) {
                const uint32_t cb = (uint32_t)(tid & 3) * 32 + j * 16;
                const uint32_t off = swz((uint32_t)r * 128 + cb);
                cp_async16(bufb + off,        (const char*)(Kh_ + gk)      + cb);
                cp_async16(bufb + 8192 + off, (const char*)(Kh_ + gk + 64) + cb);
            }
        }
        {
            const int r = tid >> 1;
            const size_t gv = voff + (size_t)r * SEQ + (size_t)it * 64;
            #pragma unroll
            for (int j = 0; j < 2; j++) {
                const uint32_t cb = (uint32_t)(tid & 1) * 64 + j * 32;
                const uint32_t off0 = swz((uint32_t)r * 128 + cb);
                const uint32_t off1 = swz((uint32_t)r * 128 + cb + 16);
                cp_async16(bufb + 16384 + off0, (const char*)(Vh_ + gv) + cb);
                cp_async16(bufb + 16384 + off1, (const char*)(Vh_ + gv) + cb + 16);
            }
        }
        CP_COMMIT();
    };

    fill_kv(0);

    const int nl = (lane & 7) + ((lane >> 4) & 1) * 8;
    const int kh = (lane >> 3) & 1;
    const uint32_t arow = (uint32_t)(wid * 16 + (lane & 15));
    const uint32_t acol16 = (uint32_t)(((lane >> 4) & 1) * 16);

    float O[16][4];
    #pragma unroll
    for (int j = 0; j < 16; j++)
        #pragma unroll
        for (int q = 0; q < 4; q++) O[j][q] = 0.0f;
    float mrun[2] = {-1e30f, -1e30f}, lrun[2] = {0.0f, 0.0f};

    for (int it = 0; it < SEQ / 64; ++it) {
        CP_WAIT(0);
        __syncthreads();
        if (it + 1 < SEQ / 64) fill_kv(it + 1);
        const uint32_t kb = sb + FL_KV0 + (uint32_t)(it & 1) * 32768;

        float S[8][4];
        #pragma unroll
        for (int nf = 0; nf < 8; nf++)
            #pragma unroll
            for (int q = 0; q < 4; q++) S[nf][q] = 0.0f;

        #pragma unroll
        for (int ks = 0; ks < 8; ++ks) {
            const uint32_t qp = sb + (uint32_t)(ks >> 2) * 16384;
            const uint32_t kp = kb + (uint32_t)(ks >> 2) * 8192;
            const uint32_t ac = acol16 + (uint32_t)(ks & 3) * 32;
            uint32_t qh[4];
            ldsm4(qh, qp + swz(arow * 128 + ac));
            uint32_t bh2[8][2];
            #pragma unroll
            for (int g = 0; g < 4; g++) {
                const uint32_t ro = (uint32_t)(nl + g * 16) * 128
                                  + kh * 16 + (ks & 3) * 32;
                uint32_t t[4];
                ldsm4(t, kp + swz(ro));
                bh2[2*g][0] = t[0]; bh2[2*g][1] = t[1];
                bh2[2*g+1][0] = t[2]; bh2[2*g+1][1] = t[3];
            }
            #pragma unroll
            for (int nf = 0; nf < 8; nf++)
                mma16816(S[nf], qh, bh2[nf][0], bh2[nf][1]);
        }

        float mx0 = -1e30f, mx1 = -1e30f;
        #pragma unroll
        for (int nf = 0; nf < 8; nf++) {
            mx0 = fmaxf(mx0, fmaxf(S[nf][0], S[nf][1]));
            mx1 = fmaxf(mx1, fmaxf(S[nf][2], S[nf][3]));
        }
        mx0 = fmaxf(mx0, __shfl_xor_sync(0xffffffffu, mx0, 1));
        mx0 = fmaxf(mx0, __shfl_xor_sync(0xffffffffu, mx0, 2));
        mx1 = fmaxf(mx1, __shfl_xor_sync(0xffffffffu, mx1, 1));
        mx1 = fmaxf(mx1, __shfl_xor_sync(0xffffffffu, mx1, 2));
        const float mn0 = fmaxf(mrun[0], mx0);
        const float mn1 = fmaxf(mrun[1], mx1);
        const float fac0 = exp2f(mrun[0] - mn0);
        const float fac1 = exp2f(mrun[1] - mn1);
        mrun[0] = mn0; mrun[1] = mn1;

        uint32_t P[4][4];
        float rs0 = 0.0f, rs1 = 0.0f;
        #pragma unroll
        for (int ks = 0; ks < 4; ++ks) {
            #pragma unroll
            for (int j = 0; j < 2; j++) {
                const int nf = 2 * ks + j;
                const uint32_t p0 = ex2_f16x2(cvt_f16x2(S[nf][0] - mn0, S[nf][1] - mn0));
                const uint32_t p1 = ex2_f16x2(cvt_f16x2(S[nf][2] - mn1, S[nf][3] - mn1));
                P[ks][2 * j]     = p0;
                P[ks][2 * j + 1] = p1;
                rs0 += sum_f16x2(p0);
                rs1 += sum_f16x2(p1);
            }
        }
        rs0 += __shfl_xor_sync(0xffffffffu, rs0, 1);
        rs0 += __shfl_xor_sync(0xffffffffu, rs0, 2);
        rs1 += __shfl_xor_sync(0xffffffffu, rs1, 1);
        rs1 += __shfl_xor_sync(0xffffffffu, rs1, 2);
        lrun[0] = lrun[0] * fac0 + rs0;
        lrun[1] = lrun[1] * fac1 + rs1;

        #pragma unroll
        for (int nf = 0; nf < 16; nf++) {
            O[nf][0] *= fac0; O[nf][1] *= fac0;
            O[nf][2] *= fac1; O[nf][3] *= fac1;
        }

        #pragma unroll
        for (int ks = 0; ks < 4; ++ks) {
            uint32_t vh2[16][2];
            #pragma unroll
            for (int g = 0; g < 8; g++) {
                const uint32_t ro = (uint32_t)(nl + g * 16) * 128
                                  + kh * 16 + ks * 32;
                uint32_t t[4];
                ldsm4(t, kb + 16384 + swz(ro));
                vh2[2*g][0] = t[0]; vh2[2*g][1] = t[1];
                vh2[2*g+1][0] = t[2]; vh2[2*g+1][1] = t[3];
            }
            #pragma unroll
            for (int nf = 0; nf < 16; nf++)
                mma16816(O[nf], P[ks], vh2[nf][0], vh2[nf][1]);
        }
    }

    const float linv0 = 1.0f / lrun[0];
    const float linv1 = 1.0f / lrun[1];
    const int b = bh >> 4, h = bh & 15;
    const int r = qt * 128 + wid * 16 + (lane >> 2);
    #pragma unroll
    for (int nf = 0; nf < 16; nf++) {
        const int c = nf * 8 + (lane & 3) * 2;
        const size_t base = ((size_t)b * SEQ + r) * HID + (size_t)h * 128 + c;
        *(uint32_t*)(Ah_ + base) = hf2pack(O[nf][0] * linv0, O[nf][1] * linv0);
        *(uint32_t*)(Ah_ + base + (size_t)8 * HID) =
            hf2pack(O[nf][2] * linv1, O[nf][3] * linv1);
    }
}

// ============================================================================
// Conversions
// ============================================================================
__global__ __launch_bounds__(256)
void conv_round_h(const float4* __restrict__ in, uint32_t* __restrict__ hi, int n4)
{
    int i = blockIdx.x * blockDim.x + threadIdx.x;
    if (i >= n4) return;
    float4 v = in[i];
    hi[2 * i]     = hf2pack(v.x, v.y);
    hi[2 * i + 1] = hf2pack(v.z, v.w);
}

__global__ __launch_bounds__(256)
void conv_round_h4(const float4* __restrict__ w0, const float4* __restrict__ w1,
                   const float4* __restrict__ w2, const float4* __restrict__ w3,
                   uint32_t* __restrict__ o0, uint32_t* __restrict__ o1,
                   uint32_t* __restrict__ o2, uint32_t* __restrict__ o3, int n4)
{
    int i = blockIdx.x * blockDim.x + threadIdx.x;
    if (i >= n4) return;
    const float4* in = (blockIdx.y == 0) ? w0 : (blockIdx.y == 1) ? w1
                     : (blockIdx.y == 2) ? w2 : w3;
    uint32_t* hi = (blockIdx.y == 0) ? o0 : (blockIdx.y == 1) ? o1
                 : (blockIdx.y == 2) ? o2 : o3;
    float4 v = in[i];
    hi[2 * i]     = hf2pack(v.x, v.y);
    hi[2 * i + 1] = hf2pack(v.z, v.w);
}

// ============================================================================
// kernel_launch
// ============================================================================
extern "C" void kernel_launch(void* const* d_in, const int* in_sizes, int n_in,
                              void* d_out, int out_size)
{
    const float* x  = (const float*)d_in[0];
    const float* Wq = (const float*)d_in[1];
    const float* bq = (const float*)d_in[2];
    const float* Wk = (const float*)d_in[3];
    const float* bk = (const float*)d_in[4];
    const float* Wv = (const float*)d_in[5];
    const float* bv = (const float*)d_in[6];
    const float* Wo = (const float*)d_in[7];
    const float* bo = (const float*)d_in[8];
    float* out = (float*)d_out;

    unsigned char* pool;
    cudaGetSymbolAddress((void**)&pool, g_pool);
    auto hfp = [&](size_t off) { return (__half*)(pool + off); };
    auto u32 = [&](size_t off) { return (uint32_t*)(pool + off); };

    cudaFuncSetAttribute(qkv_mma,    cudaFuncAttributeMaxDynamicSharedMemorySize, SMEM_BYTES);
    cudaFuncSetAttribute(gemm_out,   cudaFuncAttributeMaxDynamicSharedMemorySize, SMEM_BYTES);
    cudaFuncSetAttribute(flash_attn, cudaFuncAttributeMaxDynamicSharedMemorySize, FL_SMEM);

    // 1/sqrt(128) * log2(e): scores come out in log2 domain
    const float scale = 0.08838834764831845f * 1.44269504088896340736f;

    // 1) conversions
    conv_round_h<<<8192, 256>>>((const float4*)x, u32(OFF_XH), 2097152);
    dim3 gW(4096, 4, 1);
    conv_round_h4<<<gW, 256>>>((const float4*)Wq, (const float4*)Wk,
                               (const float4*)Wv, (const float4*)Wo,
                               u32(OFF_WQH), u32(OFF_WKH),
                               u32(OFF_WVH), u32(OFF_WOH), 1048576);

    // 2) fused QKV projections (3-stage pipelined GEMM)
    dim3 gQKV(16, 32, 3);
    qkv_mma<<<gQKV, 256, SMEM_BYTES>>>(
        hfp(OFF_XH),
        hfp(OFF_WQH), hfp(OFF_WKH), hfp(OFF_WVH),
        bq, bk, bv,
        hfp(OFF_QH), hfp(OFF_KH), hfp(OFF_VTH), scale);

    // 3) fused flash attention (R12 proven version)
    dim3 gF(SEQ / 128, BATCH * HEADS, 1);
    flash_attn<<<gF, 256, FL_SMEM>>>(hfp(OFF_QH), hfp(OFF_KH),
                                     hfp(OFF_VTH), hfp(OFF_AH));

    // 4) output projection
    dim3 gO(16, 32, 1);
    gemm_out<<<gO, 256, SMEM_BYTES>>>(hfp(OFF_AH), hfp(OFF_WOH), out, bo);
}

// round 15
// speedup vs baseline: 1.1216x; 1.0636x over previous
#include <cuda_runtime.h>
#include <cuda_fp16.h>
#include <cstdint>
#include <cstddef>

// ============================================================================
// Problem constants
// ============================================================================
constexpr int SEQ = 2048, HID = 2048, HEADS = 16, HD = 128, BATCH = 2;
constexpr int TILEB  = 128 * 80;          // 128x32-fp16 tile, 80B padded rows
constexpr int STAGEB = 2 * TILEB;         // A, B tiles (20 KB)
constexpr int SMEM_BYTES = 67584;         // max(3*STAGEB=61440, transpose 128*132*4)

// ============================================================================
// Device scratch pool (all fp16)
// ============================================================================
constexpr size_t MB = 1048576ull;
constexpr size_t OFF_XH  = 0;
constexpr size_t OFF_WQH = 16*MB;
constexpr size_t OFF_WKH = 24*MB;
constexpr size_t OFF_WVH = 32*MB;
constexpr size_t OFF_WOH = 40*MB;
constexpr size_t OFF_QH  = 48*MB;      // Q fp16 (scale*log2e folded in)
constexpr size_t OFF_KH  = 64*MB;
constexpr size_t OFF_VTH = 80*MB;      // V^T fp16
constexpr size_t OFF_AH  = 96*MB;      // attn fp16
constexpr size_t POOL_SZ = 112*MB;

__device__ __align__(1024) unsigned char g_pool[POOL_SZ];

// ============================================================================
// Helpers
// ============================================================================
__device__ __forceinline__ uint32_t smem_u32(const void* p) {
    uint32_t a;
    asm("{ .reg .u64 t; cvta.to.shared.u64 t, %1; cvt.u32.u64 %0, t; }"
        : "=r"(a) : "l"(p));
    return a;
}
__device__ __forceinline__ void cp_async16(uint32_t dst, const void* src) {
    asm volatile("cp.async.cg.shared.global [%0], [%1], 16;"
                 :: "r"(dst), "l"(src) : "memory");
}
#define CP_COMMIT() asm volatile("cp.async.commit_group;" ::: "memory")
#define CP_WAIT(n)  asm volatile("cp.async.wait_group %0;" :: "n"(n) : "memory")

__device__ __forceinline__ void ldsm4(uint32_t r[4], uint32_t a) {
    asm volatile("ldmatrix.sync.aligned.m8n8.x4.shared.b16 {%0,%1,%2,%3}, [%4];"
                 : "=r"(r[0]), "=r"(r[1]), "=r"(r[2]), "=r"(r[3]) : "r"(a));
}
__device__ __forceinline__ void mma16816(float c[4], const uint32_t a[4],
                                         const uint32_t b0, const uint32_t b1) {
    asm volatile(
        "mma.sync.aligned.m16n8k16.row.col.f32.f16.f16.f32 "
        "{%0,%1,%2,%3}, {%4,%5,%6,%7}, {%8,%9}, {%0,%1,%2,%3};"
        : "+f"(c[0]), "+f"(c[1]), "+f"(c[2]), "+f"(c[3])
        : "r"(a[0]), "r"(a[1]), "r"(a[2]), "r"(a[3]), "r"(b0), "r"(b1));
}
__device__ __forceinline__ uint32_t hf2pack(float a, float b) {
    __half2 t;
    t.x = __float2half_rn(a);
    t.y = __float2half_rn(b);
    return *reinterpret_cast<uint32_t*>(&t);
}
__device__ __forceinline__ uint32_t cvt_f16x2(float lo, float hi) {
    uint32_t d;
    asm("cvt.rn.f16x2.f32 %0, %1, %2;" : "=r"(d) : "f"(hi), "f"(lo));
    return d;
}
__device__ __forceinline__ uint32_t ex2_f16x2(uint32_t s) {
    uint32_t d;
    asm("ex2.approx.f16x2 %0, %1;" : "=r"(d) : "r"(s));
    return d;
}
__device__ __forceinline__ float sum_f16x2(uint32_t p) {
    __half2 h = *reinterpret_cast<__half2*>(&p);
    float2 f = __half22float2(h);
    return f.x + f.y;
}
__device__ __forceinline__ uint32_t swz(uint32_t o) { return o ^ ((o >> 3) & 0x70); }

// ============================================================================
// fp16 GEMM mainloop: acc = A @ B^T, 128x128, BK=32.
// 3-stage cp.async pipeline, ONE __syncthreads per iteration (fill issued
// after the barrier — same ordering the flash kernel uses).
// ============================================================================
__device__ __forceinline__ void mma_mainloop(
    uint32_t sb, const __half* pAh, const __half* pBh,
    int lda, int ldb, int K, int tid, float acc[2][8][4])
{
    const int lane = tid & 31, wid = tid >> 5;
    const int wm = wid & 3, wn = wid >> 2;
    const int frow = tid >> 2, fch = tid & 3;
    const uint32_t fdst = (uint32_t)frow * 80 + (uint32_t)fch * 16;

    #define FILL_TILE(dstBase, g, ld) do {                                      \
        const char* _g = (const char*)(g) + ((size_t)_k0 + fch * 8) * 2;        \
        cp_async16((dstBase) + fdst, _g + (size_t)frow * (ld) * 2);             \
        cp_async16((dstBase) + fdst + 64 * 80, _g + (size_t)(frow + 64) * (ld) * 2); \
    } while (0)

    #define FILL_STAGE(IT, SQ) do {                                             \
        const uint32_t _st = sb + (uint32_t)(SQ) * STAGEB;                      \
        const int _k0 = (IT) * 32;                                              \
        FILL_TILE(_st, pAh, lda);                                               \
        FILL_TILE(_st + TILEB, pBh, ldb);                                       \
        CP_COMMIT();                                                            \
    } while (0)

    const uint32_t aOff = (uint32_t)(wm * 32 + (lane & 15)) * 80
                        + (uint32_t)((lane >> 4) & 1) * 16;
    const int nl = (lane & 7) + ((lane >> 4) & 1) * 8;
    const int kh = (lane >> 3) & 1;
    const uint32_t bOff = (uint32_t)(wn * 64 + nl) * 80 + (uint32_t)kh * 16;

    const int NIT = K >> 5;
    FILL_STAGE(0, 0);
    FILL_STAGE(1, 1);

    int sq = 0;        // it % 3 (rotating)
    int fq = 2;        // (it + 2) % 3 (rotating fill slot)
    for (int it = 0; it < NIT; ++it) {
        if (it + 1 < NIT) { CP_WAIT(1); }
        else              { CP_WAIT(0); }
        __syncthreads();
        if (it + 2 < NIT) FILL_STAGE(it + 2, fq);
        const uint32_t st = sb + (uint32_t)sq * STAGEB;
        #pragma unroll
        for (int ks = 0; ks < 2; ks++) {
            uint32_t th[2][4];
            ldsm4(th[0], st + TILEB + bOff + ks * 32);
            uint32_t ahf[2][4];
            #pragma unroll
            for (int mf = 0; mf < 2; mf++)
                ldsm4(ahf[mf], st + aOff + mf * (16 * 80) + ks * 32);
            #pragma unroll
            for (int nq = 0; nq < 4; nq++) {
                const int cur = nq & 1;
                if (nq < 3) {
                    ldsm4(th[cur ^ 1],
                          st + TILEB + bOff + (nq + 1) * (16 * 80) + ks * 32);
                }
                #pragma unroll
                for (int mf = 0; mf < 2; mf++) {
                    mma16816(acc[mf][2 * nq],     ahf[mf], th[cur][0], th[cur][1]);
                    mma16816(acc[mf][2 * nq + 1], ahf[mf], th[cur][2], th[cur][3]);
                }
            }
        }
        sq = (sq == 2) ? 0 : sq + 1;
        fq = (fq == 2) ? 0 : fq + 1;
    }
    __syncthreads();   // protect smem reuse in epilogues
    #undef FILL_STAGE
    #undef FILL_TILE
}

// ============================================================================
// Fused QKV projection (scale includes log2e)
// ============================================================================
__global__ void __launch_bounds__(256, 2)
qkv_mma(const __half* __restrict__ Xh,
        const __half* __restrict__ Wqh, const __half* __restrict__ Wkh,
        const __half* __restrict__ Wvh,
        const float* __restrict__ bq, const float* __restrict__ bk,
        const float* __restrict__ bv,
        __half* __restrict__ Qh, __half* __restrict__ Kh,
        __half* __restrict__ VTh, float scale)
{
    extern __shared__ __align__(128) unsigned char smem[];
    const uint32_t sb = smem_u32(smem);
    const int tid = threadIdx.x, lane = tid & 31, wid = tid >> 5;
    const int wm = wid & 3, wn = wid >> 2;
    const int bx = blockIdx.x, by = blockIdx.y, bz = blockIdx.z;

    const __half* Bh = (bz == 0) ? Wqh : (bz == 1) ? Wkh : Wvh;
    const float* bias = (bz == 0) ? bq : (bz == 1) ? bk : bv;
    const float alpha = (bz == 0) ? scale : 1.0f;

    const __half* pAh = Xh + (size_t)by * 128 * HID;
    const __half* pBh = Bh + (size_t)bx * 128 * HID;

    float acc[2][8][4];
    #pragma unroll
    for (int i = 0; i < 2; i++)
        #pragma unroll
        for (int j = 0; j < 8; j++)
            #pragma unroll
            for (int q = 0; q < 4; q++) acc[i][j][q] = 0.0f;

    mma_mainloop(sb, pAh, pBh, HID, HID, HID, tid, acc);

    const int mrow0 = wm * 32 + (lane >> 2);
    const int ncol0 = wn * 64 + (lane & 3) * 2;

    if (bz == 2) {
        float* tb = (float*)smem;  // [128][132]
        #pragma unroll
        for (int mf = 0; mf < 2; mf++)
            #pragma unroll
            for (int nf = 0; nf < 8; nf++) {
                const int r = mrow0 + mf * 16;
                const int c = ncol0 + nf * 8;
                tb[r * 132 + c]           = acc[mf][nf][0];
                tb[r * 132 + c + 1]       = acc[mf][nf][1];
                tb[(r + 8) * 132 + c]     = acc[mf][nf][2];
                tb[(r + 8) * 132 + c + 1] = acc[mf][nf][3];
            }
        __syncthreads();
        const int d = tid & 127, sh = tid >> 7;
        const float bvv = bias[bx * 128 + d];
        const int b = by >> 4;
        const size_t base = (((size_t)(b * HEADS + bx)) * HD + d) * SEQ
                          + (size_t)(by & 15) * 128 + sh * 64;
        #pragma unroll 8
        for (int s = 0; s < 64; s += 2) {
            float v0 = tb[(sh * 64 + s) * 132 + d] + bvv;
            float v1 = tb[(sh * 64 + s + 1) * 132 + d] + bvv;
            *(uint32_t*)(VTh + base + s) = hf2pack(v0, v1);
        }
        return;
    }

    __half* Ch = (bz == 0) ? Qh : Kh;
    #pragma unroll
    for (int mf = 0; mf < 2; mf++)
        #pragma unroll
        for (int nf = 0; nf < 8; nf++) {
            const int r = by * 128 + mrow0 + mf * 16;
            const int c = ncol0 + nf * 8;
            const float* a = acc[mf][nf];
            const int b = r >> 11, s = r & 2047;
            const float b0 = bias[bx * 128 + c], b1 = bias[bx * 128 + c + 1];
            const size_t base = (((size_t)(b * HEADS + bx)) * SEQ + s) * HD + c;
            *(uint32_t*)(Ch + base) =
                hf2pack((a[0] + b0) * alpha, (a[1] + b1) * alpha);
            *(uint32_t*)(Ch + base + (size_t)8 * HD) =
                hf2pack((a[2] + b0) * alpha, (a[3] + b1) * alpha);
        }
}

// ============================================================================
// Output projection GEMM
// ============================================================================
__global__ void __launch_bounds__(256, 2)
gemm_out(const __half* __restrict__ Ah, const __half* __restrict__ Bh,
         float* __restrict__ Cf, const float* __restrict__ bias)
{
    extern __shared__ __align__(128) unsigned char smem[];
    const uint32_t sb = smem_u32(smem);
    const int tid = threadIdx.x, lane = tid & 31, wid = tid >> 5;
    const int wm = wid & 3, wn = wid >> 2;
    const int bx = blockIdx.x, by = blockIdx.y;

    const __half* pAh = Ah + (size_t)by * 128 * HID;
    const __half* pBh = Bh + (size_t)bx * 128 * HID;

    float acc[2][8][4];
    #pragma unroll
    for (int i = 0; i < 2; i++)
        #pragma unroll
        for (int j = 0; j < 8; j++)
            #pragma unroll
            for (int q = 0; q < 4; q++) acc[i][j][q] = 0.0f;

    mma_mainloop(sb, pAh, pBh, HID, HID, HID, tid, acc);

    const int mrow0 = wm * 32 + (lane >> 2);
    const int ncol0 = wn * 64 + (lane & 3) * 2;
    #pragma unroll
    for (int mf = 0; mf < 2; mf++)
        #pragma unroll
        for (int nf = 0; nf < 8; nf++) {
            const int r = by * 128 + mrow0 + mf * 16;
            const int c = ncol0 + nf * 8;
            const float* a = acc[mf][nf];
            const float b0 = bias[bx * 128 + c], b1 = bias[bx * 128 + c + 1];
            float* p0 = Cf + (size_t)r * HID + (size_t)bx * 128 + c;
            float2 w0; w0.x = a[0] + b0; w0.y = a[1] + b1;
            float2 w1; w1.x = a[2] + b0; w1.y = a[3] + b1;
            *(float2*)p0 = w0;
            *(float2*)(p0 + (size_t)8 * HID) = w1;
        }
}

// ============================================================================
// Fused flash attention — EXACT R12 version (proven 253.5 us)
// ============================================================================
constexpr int FL_KV0  = 32768;
constexpr int FL_SMEM = 98304;

__global__ void __launch_bounds__(256, 1)
flash_attn(const __half* __restrict__ Qh_, const __half* __restrict__ Kh_,
           const __half* __restrict__ Vh_, __half* __restrict__ Ah_)
{
    extern __shared__ __align__(128) unsigned char smem[];
    const uint32_t sb = smem_u32(smem);
    const int tid = threadIdx.x, lane = tid & 31, wid = tid >> 5;
    const int qt = blockIdx.x, bh = blockIdx.y;

    const size_t qoff = ((size_t)bh * SEQ + (size_t)qt * 128) * HD;
    const size_t koff = (size_t)bh * SEQ * HD;
    const size_t voff = (size_t)bh * HD * SEQ;

    {
        const int r = tid >> 1;
        const size_t gq = qoff + (size_t)r * HD;
        #pragma unroll
        for (int j = 0; j < 4; j++) {
            const uint32_t cb = (uint32_t)(tid & 1) * 64 + j * 16;
            const uint32_t off = swz((uint32_t)r * 128 + cb);
            cp_async16(sb + off,         (const char*)(Qh_ + gq)      + cb);
            cp_async16(sb + 16384 + off, (const char*)(Qh_ + gq + 64) + cb);
        }
    }

    auto fill_kv = [&](int it) {
        const uint32_t bufb = sb + FL_KV0 + (uint32_t)(it & 1) * 32768;
        {
            const int r = tid >> 2;
            const size_t gk = koff + ((size_t)it * 64 + r) * HD;
            #pragma unroll
            for (int j = 0; j < 2; j++) {
                const uint32_t cb = (uint32_t)(tid & 3) * 32 + j * 16;
                const uint32_t off = swz((uint32_t)r * 128 + cb);
                cp_async16(bufb + off,        (const char*)(Kh_ + gk)      + cb);
                cp_async16(bufb + 8192 + off, (const char*)(Kh_ + gk + 64) + cb);
            }
        }
        {
            const int r = tid >> 1;
            const size_t gv = voff + (size_t)r * SEQ + (size_t)it * 64;
            #pragma unroll
            for (int j = 0; j < 2; j++) {
                const uint32_t cb = (uint32_t)(tid & 1) * 64 + j * 32;
                const uint32_t off0 = swz((uint32_t)r * 128 + cb);
                const uint32_t off1 = swz((uint32_t)r * 128 + cb + 16);
                cp_async16(bufb + 16384 + off0, (const char*)(Vh_ + gv) + cb);
                cp_async16(bufb + 16384 + off1, (const char*)(Vh_ + gv) + cb + 16);
            }
        }
        CP_COMMIT();
    };

    fill_kv(0);

    const int nl = (lane & 7) + ((lane >> 4) & 1) * 8;
    const int kh = (lane >> 3) & 1;
    const uint32_t arow = (uint32_t)(wid * 16 + (lane & 15));
    const uint32_t acol16 = (uint32_t)(((lane >> 4) & 1) * 16);

    float O[16][4];
    #pragma unroll
    for (int j = 0; j < 16; j++)
        #pragma unroll
        for (int q = 0; q < 4; q++) O[j][q] = 0.0f;
    float mrun[2] = {-1e30f, -1e30f}, lrun[2] = {0.0f, 0.0f};

    for (int it = 0; it < SEQ / 64; ++it) {
        CP_WAIT(0);
        __syncthreads();
        if (it + 1 < SEQ / 64) fill_kv(it + 1);
        const uint32_t kb = sb + FL_KV0 + (uint32_t)(it & 1) * 32768;

        float S[8][4];
        #pragma unroll
        for (int nf = 0; nf < 8; nf++)
            #pragma unroll
            for (int q = 0; q < 4; q++) S[nf][q] = 0.0f;

        #pragma unroll
        for (int ks = 0; ks < 8; ++ks) {
            const uint32_t qp = sb + (uint32_t)(ks >> 2) * 16384;
            const uint32_t kp = kb + (uint32_t)(ks >> 2) * 8192;
            const uint32_t ac = acol16 + (uint32_t)(ks & 3) * 32;
            uint32_t qh[4];
            ldsm4(qh, qp + swz(arow * 128 + ac));
            uint32_t bh2[8][2];
            #pragma unroll
            for (int g = 0; g < 4; g++) {
                const uint32_t ro = (uint32_t)(nl + g * 16) * 128
                                  + kh * 16 + (ks & 3) * 32;
                uint32_t t[4];
                ldsm4(t, kp + swz(ro));
                bh2[2*g][0] = t[0]; bh2[2*g][1] = t[1];
                bh2[2*g+1][0] = t[2]; bh2[2*g+1][1] = t[3];
            }
            #pragma unroll
            for (int nf = 0; nf < 8; nf++)
                mma16816(S[nf], qh, bh2[nf][0], bh2[nf][1]);
        }

        float mx0 = -1e30f, mx1 = -1e30f;
        #pragma unroll
        for (int nf = 0; nf < 8; nf++) {
            mx0 = fmaxf(mx0, fmaxf(S[nf][0], S[nf][1]));
            mx1 = fmaxf(mx1, fmaxf(S[nf][2], S[nf][3]));
        }
        mx0 = fmaxf(mx0, __shfl_xor_sync(0xffffffffu, mx0, 1));
        mx0 = fmaxf(mx0, __shfl_xor_sync(0xffffffffu, mx0, 2));
        mx1 = fmaxf(mx1, __shfl_xor_sync(0xffffffffu, mx1, 1));
        mx1 = fmaxf(mx1, __shfl_xor_sync(0xffffffffu, mx1, 2));
        const float mn0 = fmaxf(mrun[0], mx0);
        const float mn1 = fmaxf(mrun[1], mx1);
        const float fac0 = exp2f(mrun[0] - mn0);
        const float fac1 = exp2f(mrun[1] - mn1);
        mrun[0] = mn0; mrun[1] = mn1;

        uint32_t P[4][4];
        float rs0 = 0.0f, rs1 = 0.0f;
        #pragma unroll
        for (int ks = 0; ks < 4; ++ks) {
            #pragma unroll
            for (int j = 0; j < 2; j++) {
                const int nf = 2 * ks + j;
                const uint32_t p0 = ex2_f16x2(cvt_f16x2(S[nf][0] - mn0, S[nf][1] - mn0));
                const uint32_t p1 = ex2_f16x2(cvt_f16x2(S[nf][2] - mn1, S[nf][3] - mn1));
                P[ks][2 * j]     = p0;
                P[ks][2 * j + 1] = p1;
                rs0 += sum_f16x2(p0);
                rs1 += sum_f16x2(p1);
            }
        }
        rs0 += __shfl_xor_sync(0xffffffffu, rs0, 1);
        rs0 += __shfl_xor_sync(0xffffffffu, rs0, 2);
        rs1 += __shfl_xor_sync(0xffffffffu, rs1, 1);
        rs1 += __shfl_xor_sync(0xffffffffu, rs1, 2);
        lrun[0] = lrun[0] * fac0 + rs0;
        lrun[1] = lrun[1] * fac1 + rs1;

        #pragma unroll
        for (int nf = 0; nf < 16; nf++) {
            O[nf][0] *= fac0; O[nf][1] *= fac0;
            O[nf][2] *= fac1; O[nf][3] *= fac1;
        }

        #pragma unroll
        for (int ks = 0; ks < 4; ++ks) {
            uint32_t vh2[16][2];
            #pragma unroll
            for (int g = 0; g < 8; g++) {
                const uint32_t ro = (uint32_t)(nl + g * 16) * 128
                                  + kh * 16 + ks * 32;
                uint32_t t[4];
                ldsm4(t, kb + 16384 + swz(ro));
                vh2[2*g][0] = t[0]; vh2[2*g][1] = t[1];
                vh2[2*g+1][0] = t[2]; vh2[2*g+1][1] = t[3];
            }
            #pragma unroll
            for (int nf = 0; nf < 16; nf++)
                mma16816(O[nf], P[ks], vh2[nf][0], vh2[nf][1]);
        }
    }

    const float linv0 = 1.0f / lrun[0];
    const float linv1 = 1.0f / lrun[1];
    const int b = bh >> 4, h = bh & 15;
    const int r = qt * 128 + wid * 16 + (lane >> 2);
    #pragma unroll
    for (int nf = 0; nf < 16; nf++) {
        const int c = nf * 8 + (lane & 3) * 2;
        const size_t base = ((size_t)b * SEQ + r) * HID + (size_t)h * 128 + c;
        *(uint32_t*)(Ah_ + base) = hf2pack(O[nf][0] * linv0, O[nf][1] * linv0);
        *(uint32_t*)(Ah_ + base + (size_t)8 * HID) =
            hf2pack(O[nf][2] * linv1, O[nf][3] * linv1);
    }
}

// ============================================================================
// Conversions
// ============================================================================
__global__ __launch_bounds__(256)
void conv_round_h(const float4* __restrict__ in, uint32_t* __restrict__ hi, int n4)
{
    int i = blockIdx.x * blockDim.x + threadIdx.x;
    if (i >= n4) return;
    float4 v = in[i];
    hi[2 * i]     = hf2pack(v.x, v.y);
    hi[2 * i + 1] = hf2pack(v.z, v.w);
}

__global__ __launch_bounds__(256)
void conv_round_h4(const float4* __restrict__ w0, const float4* __restrict__ w1,
                   const float4* __restrict__ w2, const float4* __restrict__ w3,
                   uint32_t* __restrict__ o0, uint32_t* __restrict__ o1,
                   uint32_t* __restrict__ o2, uint32_t* __restrict__ o3, int n4)
{
    int i = blockIdx.x * blockDim.x + threadIdx.x;
    if (i >= n4) return;
    const float4* in = (blockIdx.y == 0) ? w0 : (blockIdx.y == 1) ? w1
                     : (blockIdx.y == 2) ? w2 : w3;
    uint32_t* hi = (blockIdx.y == 0) ? o0 : (blockIdx.y == 1) ? o1
                 : (blockIdx.y == 2) ? o2 : o3;
    float4 v = in[i];
    hi[2 * i]     = hf2pack(v.x, v.y);
    hi[2 * i + 1] = hf2pack(v.z, v.w);
}

// ============================================================================
// kernel_launch
// ============================================================================
extern "C" void kernel_launch(void* const* d_in, const int* in_sizes, int n_in,
                              void* d_out, int out_size)
{
    const float* x  = (const float*)d_in[0];
    const float* Wq = (const float*)d_in[1];
    const float* bq = (const float*)d_in[2];
    const float* Wk = (const float*)d_in[3];
    const float* bk = (const float*)d_in[4];
    const float* Wv = (const float*)d_in[5];
    const float* bv = (const float*)d_in[6];
    const float* Wo = (const float*)d_in[7];
    const float* bo = (const float*)d_in[8];
    float* out = (float*)d_out;

    unsigned char* pool;
    cudaGetSymbolAddress((void**)&pool, g_pool);
    auto hfp = [&](size_t off) { return (__half*)(pool + off); };
    auto u32 = [&](size_t off) { return (uint32_t*)(pool + off); };

    cudaFuncSetAttribute(qkv_mma,    cudaFuncAttributeMaxDynamicSharedMemorySize, SMEM_BYTES);
    cudaFuncSetAttribute(gemm_out,   cudaFuncAttributeMaxDynamicSharedMemorySize, SMEM_BYTES);
    cudaFuncSetAttribute(flash_attn, cudaFuncAttributeMaxDynamicSharedMemorySize, FL_SMEM);

    // 1/sqrt(128) * log2(e): scores come out in log2 domain
    const float scale = 0.08838834764831845f * 1.44269504088896340736f;

    // 1) conversions
    conv_round_h<<<8192, 256>>>((const float4*)x, u32(OFF_XH), 2097152);
    dim3 gW(4096, 4, 1);
    conv_round_h4<<<gW, 256>>>((const float4*)Wq, (const float4*)Wk,
                               (const float4*)Wv, (const float4*)Wo,
                               u32(OFF_WQH), u32(OFF_WKH),
                               u32(OFF_WVH), u32(OFF_WOH), 1048576);

    // 2) fused QKV projections (3-stage, single-sync pipelined GEMM)
    dim3 gQKV(16, 32, 3);
    qkv_mma<<<gQKV, 256, SMEM_BYTES>>>(
        hfp(OFF_XH),
        hfp(OFF_WQH), hfp(OFF_WKH), hfp(OFF_WVH),
        bq, bk, bv,
        hfp(OFF_QH), hfp(OFF_KH), hfp(OFF_VTH), scale);

    // 3) fused flash attention (R12 proven version)
    dim3 gF(SEQ / 128, BATCH * HEADS, 1);
    flash_attn<<<gF, 256, FL_SMEM>>>(hfp(OFF_QH), hfp(OFF_KH),
                                     hfp(OFF_VTH), hfp(OFF_AH));

    // 4) output projection
    dim3 gO(16, 32, 1);
    gemm_out<<<gO, 256, SMEM_BYTES>>>(hfp(OFF_AH), hfp(OFF_WOH), out, bo);
}

// round 16
// speedup vs baseline: 1.2040x; 1.0735x over previous
#include <cuda_runtime.h>
#include <cuda_fp16.h>
#include <cstdint>
#include <cstddef>

// ============================================================================
// Problem constants
// ============================================================================
constexpr int SEQ = 2048, HID = 2048, HEADS = 16, HD = 128, BATCH = 2;
constexpr int TILEB  = 128 * 80;          // 128x32-fp16 tile, 80B padded rows
constexpr int STAGEB = 2 * TILEB;         // A, B tiles (20 KB)
constexpr int SMEM_BYTES = 67584;         // max(3*STAGEB=61440, transpose 128*132*4)

// ============================================================================
// Device scratch pool (all fp16)
// ============================================================================
constexpr size_t MB = 1048576ull;
constexpr size_t OFF_XH  = 0;
constexpr size_t OFF_WQH = 16*MB;
constexpr size_t OFF_WKH = 24*MB;
constexpr size_t OFF_WVH = 32*MB;
constexpr size_t OFF_WOH = 40*MB;
constexpr size_t OFF_QH  = 48*MB;      // Q fp16 (scale*log2e folded in)
constexpr size_t OFF_KH  = 64*MB;
constexpr size_t OFF_VTH = 80*MB;      // V^T fp16
constexpr size_t OFF_AH  = 96*MB;      // attn fp16
constexpr size_t POOL_SZ = 112*MB;

__device__ __align__(1024) unsigned char g_pool[POOL_SZ];

// ============================================================================
// Helpers
// ============================================================================
__device__ __forceinline__ uint32_t smem_u32(const void* p) {
    uint32_t a;
    asm("{ .reg .u64 t; cvta.to.shared.u64 t, %1; cvt.u32.u64 %0, t; }"
        : "=r"(a) : "l"(p));
    return a;
}
__device__ __forceinline__ void cp_async16(uint32_t dst, const void* src) {
    asm volatile("cp.async.cg.shared.global [%0], [%1], 16;"
                 :: "r"(dst), "l"(src) : "memory");
}
#define CP_COMMIT() asm volatile("cp.async.commit_group;" ::: "memory")
#define CP_WAIT(n)  asm volatile("cp.async.wait_group %0;" :: "n"(n) : "memory")

__device__ __forceinline__ void ldsm4(uint32_t r[4], uint32_t a) {
    asm volatile("ldmatrix.sync.aligned.m8n8.x4.shared.b16 {%0,%1,%2,%3}, [%4];"
                 : "=r"(r[0]), "=r"(r[1]), "=r"(r[2]), "=r"(r[3]) : "r"(a));
}
__device__ __forceinline__ void mma16816(float c[4], const uint32_t a[4],
                                         const uint32_t b0, const uint32_t b1) {
    asm volatile(
        "mma.sync.aligned.m16n8k16.row.col.f32.f16.f16.f32 "
        "{%0,%1,%2,%3}, {%4,%5,%6,%7}, {%8,%9}, {%0,%1,%2,%3};"
        : "+f"(c[0]), "+f"(c[1]), "+f"(c[2]), "+f"(c[3])
        : "r"(a[0]), "r"(a[1]), "r"(a[2]), "r"(a[3]), "r"(b0), "r"(b1));
}
__device__ __forceinline__ uint32_t hf2pack(float a, float b) {
    __half2 t;
    t.x = __float2half_rn(a);
    t.y = __float2half_rn(b);
    return *reinterpret_cast<uint32_t*>(&t);
}
__device__ __forceinline__ uint32_t cvt_f16x2(float lo, float hi) {
    uint32_t d;
    asm("cvt.rn.f16x2.f32 %0, %1, %2;" : "=r"(d) : "f"(hi), "f"(lo));
    return d;
}
__device__ __forceinline__ uint32_t ex2_f16x2(uint32_t s) {
    uint32_t d;
    asm("ex2.approx.f16x2 %0, %1;" : "=r"(d) : "r"(s));
    return d;
}
__device__ __forceinline__ float sum_f16x2(uint32_t p) {
    __half2 h = *reinterpret_cast<__half2*>(&p);
    float2 f = __half22float2(h);
    return f.x + f.y;
}
__device__ __forceinline__ uint32_t swz(uint32_t o) { return o ^ ((o >> 3) & 0x70); }

// ============================================================================
// fp16 GEMM mainloop: acc = A @ B^T, 128x128 CTA tile, BK=32.
// 128 threads, 4 warps in 2x2, each a 64x64 warp tile -> 64 ldsm4 / 256 HMMA
// per CTA-iter (was 96/256). 3-stage cp.async, one sync per iteration.
// ============================================================================
__device__ __forceinline__ void mma_mainloop(
    uint32_t sb, const __half* pAh, const __half* pBh,
    int lda, int ldb, int K, int tid, float acc[4][8][4])
{
    const int lane = tid & 31, wid = tid >> 5;
    const int wm = wid & 1;    // warp row: 64 rows
    const int wn = wid >> 1;   // warp col: 64 cols
    const int frow = tid >> 2, fch = tid & 3;   // 32 rows x 4 chunks

    #define FILL_TILE(dstBase, g, ld) do {                                      \
        const char* _g = (const char*)(g) + (size_t)_k0 * 2 + fch * 16;         \
        _Pragma("unroll")                                                       \
        for (int _j = 0; _j < 4; _j++) {                                        \
            const int _row = frow + _j * 32;                                    \
            cp_async16((dstBase) + (uint32_t)_row * 80 + fch * 16,              \
                       _g + (size_t)_row * (ld) * 2);                           \
        }                                                                       \
    } while (0)

    #define FILL_STAGE(IT, SQ) do {                                             \
        const uint32_t _st = sb + (uint32_t)(SQ) * STAGEB;                      \
        const int _k0 = (IT) * 32;                                              \
        FILL_TILE(_st, pAh, lda);                                               \
        FILL_TILE(_st + TILEB, pBh, ldb);                                       \
        CP_COMMIT();                                                            \
    } while (0)

    const uint32_t aOff = (uint32_t)(wm * 64 + (lane & 15)) * 80
                        + (uint32_t)((lane >> 4) & 1) * 16;
    const int nl = (lane & 7) + ((lane >> 4) & 1) * 8;
    const int kh = (lane >> 3) & 1;
    const uint32_t bOff = (uint32_t)(wn * 64 + nl) * 80 + (uint32_t)kh * 16;

    const int NIT = K >> 5;
    FILL_STAGE(0, 0);
    FILL_STAGE(1, 1);

    int sq = 0, fq = 2;
    for (int it = 0; it < NIT; ++it) {
        if (it + 1 < NIT) { CP_WAIT(1); }
        else              { CP_WAIT(0); }
        __syncthreads();
        if (it + 2 < NIT) FILL_STAGE(it + 2, fq);
        const uint32_t st = sb + (uint32_t)sq * STAGEB;
        #pragma unroll
        for (int ks = 0; ks < 2; ks++) {
            uint32_t bh2[8][2];
            #pragma unroll
            for (int g = 0; g < 4; g++) {
                uint32_t t[4];
                ldsm4(t, st + TILEB + bOff + g * (16 * 80) + ks * 32);
                bh2[2*g][0] = t[0]; bh2[2*g][1] = t[1];
                bh2[2*g+1][0] = t[2]; bh2[2*g+1][1] = t[3];
            }
            uint32_t ahf[4][4];
            #pragma unroll
            for (int mf = 0; mf < 4; mf++)
                ldsm4(ahf[mf], st + aOff + mf * (16 * 80) + ks * 32);
            #pragma unroll
            for (int mf = 0; mf < 4; mf++)
                #pragma unroll
                for (int nf = 0; nf < 8; nf++)
                    mma16816(acc[mf][nf], ahf[mf], bh2[nf][0], bh2[nf][1]);
        }
        sq = (sq == 2) ? 0 : sq + 1;
        fq = (fq == 2) ? 0 : fq + 1;
    }
    __syncthreads();   // protect smem reuse in epilogues
    #undef FILL_STAGE
    #undef FILL_TILE
}

// ============================================================================
// Fused QKV projection: grid (16, 32, 3), 128 threads.
// z=0 -> Q (scaled, scale includes log2e), z=1 -> K, z=2 -> V^T transposed.
// ============================================================================
__global__ void __launch_bounds__(128, 2)
qkv_mma(const __half* __restrict__ Xh,
        const __half* __restrict__ Wqh, const __half* __restrict__ Wkh,
        const __half* __restrict__ Wvh,
        const float* __restrict__ bq, const float* __restrict__ bk,
        const float* __restrict__ bv,
        __half* __restrict__ Qh, __half* __restrict__ Kh,
        __half* __restrict__ VTh, float scale)
{
    extern __shared__ __align__(128) unsigned char smem[];
    const uint32_t sb = smem_u32(smem);
    const int tid = threadIdx.x, lane = tid & 31, wid = tid >> 5;
    const int wm = wid & 1, wn = wid >> 1;
    const int bx = blockIdx.x, by = blockIdx.y, bz = blockIdx.z;

    const __half* Bh = (bz == 0) ? Wqh : (bz == 1) ? Wkh : Wvh;
    const float* bias = (bz == 0) ? bq : (bz == 1) ? bk : bv;
    const float alpha = (bz == 0) ? scale : 1.0f;

    const __half* pAh = Xh + (size_t)by * 128 * HID;
    const __half* pBh = Bh + (size_t)bx * 128 * HID;

    float acc[4][8][4];
    #pragma unroll
    for (int i = 0; i < 4; i++)
        #pragma unroll
        for (int j = 0; j < 8; j++)
            #pragma unroll
            for (int q = 0; q < 4; q++) acc[i][j][q] = 0.0f;

    mma_mainloop(sb, pAh, pBh, HID, HID, HID, tid, acc);

    const int mrow0 = wm * 64 + (lane >> 2);
    const int ncol0 = wn * 64 + (lane & 3) * 2;

    if (bz == 2) {
        float* tb = (float*)smem;  // [128][132]
        #pragma unroll
        for (int mf = 0; mf < 4; mf++)
            #pragma unroll
            for (int nf = 0; nf < 8; nf++) {
                const int r = mrow0 + mf * 16;
                const int c = ncol0 + nf * 8;
                tb[r * 132 + c]           = acc[mf][nf][0];
                tb[r * 132 + c + 1]       = acc[mf][nf][1];
                tb[(r + 8) * 132 + c]     = acc[mf][nf][2];
                tb[(r + 8) * 132 + c + 1] = acc[mf][nf][3];
            }
        __syncthreads();
        const int d = tid;  // 0..127
        const float bvv = bias[bx * 128 + d];
        const int b = by >> 4;
        const size_t base = (((size_t)(b * HEADS + bx)) * HD + d) * SEQ
                          + (size_t)(by & 15) * 128;
        #pragma unroll 8
        for (int s = 0; s < 128; s += 2) {
            float v0 = tb[s * 132 + d] + bvv;
            float v1 = tb[(s + 1) * 132 + d] + bvv;
            *(uint32_t*)(VTh + base + s) = hf2pack(v0, v1);
        }
        return;
    }

    __half* Ch = (bz == 0) ? Qh : Kh;
    #pragma unroll
    for (int mf = 0; mf < 4; mf++)
        #pragma unroll
        for (int nf = 0; nf < 8; nf++) {
            const int r = by * 128 + mrow0 + mf * 16;
            const int c = ncol0 + nf * 8;
            const float* a = acc[mf][nf];
            const int b = r >> 11, s = r & 2047;
            const float b0 = bias[bx * 128 + c], b1 = bias[bx * 128 + c + 1];
            const size_t base = (((size_t)(b * HEADS + bx)) * SEQ + s) * HD + c;
            *(uint32_t*)(Ch + base) =
                hf2pack((a[0] + b0) * alpha, (a[1] + b1) * alpha);
            *(uint32_t*)(Ch + base + (size_t)8 * HD) =
                hf2pack((a[2] + b0) * alpha, (a[3] + b1) * alpha);
        }
}

// ============================================================================
// Output projection GEMM: fp32 out = Ah @ Woh^T + bo, 128 threads.
// ============================================================================
__global__ void __launch_bounds__(128, 2)
gemm_out(const __half* __restrict__ Ah, const __half* __restrict__ Bh,
         float* __restrict__ Cf, const float* __restrict__ bias)
{
    extern __shared__ __align__(128) unsigned char smem[];
    const uint32_t sb = smem_u32(smem);
    const int tid = threadIdx.x, lane = tid & 31, wid = tid >> 5;
    const int wm = wid & 1, wn = wid >> 1;
    const int bx = blockIdx.x, by = blockIdx.y;

    const __half* pAh = Ah + (size_t)by * 128 * HID;
    const __half* pBh = Bh + (size_t)bx * 128 * HID;

    float acc[4][8][4];
    #pragma unroll
    for (int i = 0; i < 4; i++)
        #pragma unroll
        for (int j = 0; j < 8; j++)
            #pragma unroll
            for (int q = 0; q < 4; q++) acc[i][j][q] = 0.0f;

    mma_mainloop(sb, pAh, pBh, HID, HID, HID, tid, acc);

    const int mrow0 = wm * 64 + (lane >> 2);
    const int ncol0 = wn * 64 + (lane & 3) * 2;
    #pragma unroll
    for (int mf = 0; mf < 4; mf++)
        #pragma unroll
        for (int nf = 0; nf < 8; nf++) {
            const int r = by * 128 + mrow0 + mf * 16;
            const int c = ncol0 + nf * 8;
            const float* a = acc[mf][nf];
            const float b0 = bias[bx * 128 + c], b1 = bias[bx * 128 + c + 1];
            float* p0 = Cf + (size_t)r * HID + (size_t)bx * 128 + c;
            float2 w0; w0.x = a[0] + b0; w0.y = a[1] + b1;
            float2 w1; w1.x = a[2] + b0; w1.y = a[3] + b1;
            *(float2*)p0 = w0;
            *(float2*)(p0 + (size_t)8 * HID) = w1;
        }
}

// ============================================================================
// Fused flash attention — EXACT R12/R15 version (proven 253.5 us)
// ============================================================================
constexpr int FL_KV0  = 32768;
constexpr int FL_SMEM = 98304;

__global__ void __launch_bounds__(256, 1)
flash_attn(const __half* __restrict__ Qh_, const __half* __restrict__ Kh_,
           const __half* __restrict__ Vh_, __half* __restrict__ Ah_)
{
    extern __shared__ __align__(128) unsigned char smem[];
    const uint32_t sb = smem_u32(smem);
    const int tid = threadIdx.x, lane = tid & 31, wid = tid >> 5;
    const int qt = blockIdx.x, bh = blockIdx.y;

    const size_t qoff = ((size_t)bh * SEQ + (size_t)qt * 128) * HD;
    const size_t koff = (size_t)bh * SEQ * HD;
    const size_t voff = (size_t)bh * HD * SEQ;

    {
        const int r = tid >> 1;
        const size_t gq = qoff + (size_t)r * HD;
        #pragma unroll
        for (int j = 0; j < 4; j++) {
            const uint32_t cb = (uint32_t)(tid & 1) * 64 + j * 16;
            const uint32_t off = swz((uint32_t)r * 128 + cb);
            cp_async16(sb + off,         (const char*)(Qh_ + gq)      + cb);
            cp_async16(sb + 16384 + off, (const char*)(Qh_ + gq + 64) + cb);
        }
    }

    auto fill_kv = [&](int it) {
        const uint32_t bufb = sb + FL_KV0 + (uint32_t)(it & 1) * 32768;
        {
            const int r = tid >> 2;
            const size_t gk = koff + ((size_t)it * 64 + r) * HD;
            #pragma unroll
            for (int j = 0; j < 2; j++) {
                const uint32_t cb = (uint32_t)(tid & 3) * 32 + j * 16;
                const uint32_t off = swz((uint32_t)r * 128 + cb);
                cp_async16(bufb + off,        (const char*)(Kh_ + gk)      + cb);
                cp_async16(bufb + 8192 + off, (const char*)(Kh_ + gk + 64) + cb);
            }
        }
        {
            const int r = tid >> 1;
            const size_t gv = voff + (size_t)r * SEQ + (size_t)it * 64;
            #pragma unroll
            for (int j = 0; j < 2; j++) {
                const uint32_t cb = (uint32_t)(tid & 1) * 64 + j * 32;
                const uint32_t off0 = swz((uint32_t)r * 128 + cb);
                const uint32_t off1 = swz((uint32_t)r * 128 + cb + 16);
                cp_async16(bufb + 16384 + off0, (const char*)(Vh_ + gv) + cb);
                cp_async16(bufb + 16384 + off1, (const char*)(Vh_ + gv) + cb + 16);
            }
        }
        CP_COMMIT();
    };

    fill_kv(0);

    const int nl = (lane & 7) + ((lane >> 4) & 1) * 8;
    const int kh = (lane >> 3) & 1;
    const uint32_t arow = (uint32_t)(wid * 16 + (lane & 15));
    const uint32_t acol16 = (uint32_t)(((lane >> 4) & 1) * 16);

    float O[16][4];
    #pragma unroll
    for (int j = 0; j < 16; j++)
        #pragma unroll
        for (int q = 0; q < 4; q++) O[j][q] = 0.0f;
    float mrun[2] = {-1e30f, -1e30f}, lrun[2] = {0.0f, 0.0f};

    for (int it = 0; it < SEQ / 64; ++it) {
        CP_WAIT(0);
        __syncthreads();
        if (it + 1 < SEQ / 64) fill_kv(it + 1);
        const uint32_t kb = sb + FL_KV0 + (uint32_t)(it & 1) * 32768;

        float S[8][4];
        #pragma unroll
        for (int nf = 0; nf < 8; nf++)
            #pragma unroll
            for (int q = 0; q < 4; q++) S[nf][q] = 0.0f;

        #pragma unroll
        for (int ks = 0; ks < 8; ++ks) {
            const uint32_t qp = sb + (uint32_t)(ks >> 2) * 16384;
            const uint32_t kp = kb + (uint32_t)(ks >> 2) * 8192;
            const uint32_t ac = acol16 + (uint32_t)(ks & 3) * 32;
            uint32_t qh[4];
            ldsm4(qh, qp + swz(arow * 128 + ac));
            uint32_t bh2[8][2];
            #pragma unroll
            for (int g = 0; g < 4; g++) {
                const uint32_t ro = (uint32_t)(nl + g * 16) * 128
                                  + kh * 16 + (ks & 3) * 32;
                uint32_t t[4];
                ldsm4(t, kp + swz(ro));
                bh2[2*g][0] = t[0]; bh2[2*g][1] = t[1];
                bh2[2*g+1][0] = t[2]; bh2[2*g+1][1] = t[3];
            }
            #pragma unroll
            for (int nf = 0; nf < 8; nf++)
                mma16816(S[nf], qh, bh2[nf][0], bh2[nf][1]);
        }

        float mx0 = -1e30f, mx1 = -1e30f;
        #pragma unroll
        for (int nf = 0; nf < 8; nf++) {
            mx0 = fmaxf(mx0, fmaxf(S[nf][0], S[nf][1]));
            mx1 = fmaxf(mx1, fmaxf(S[nf][2], S[nf][3]));
        }
        mx0 = fmaxf(mx0, __shfl_xor_sync(0xffffffffu, mx0, 1));
        mx0 = fmaxf(mx0, __shfl_xor_sync(0xffffffffu, mx0, 2));
        mx1 = fmaxf(mx1, __shfl_xor_sync(0xffffffffu, mx1, 1));
        mx1 = fmaxf(mx1, __shfl_xor_sync(0xffffffffu, mx1, 2));
        const float mn0 = fmaxf(mrun[0], mx0);
        const float mn1 = fmaxf(mrun[1], mx1);
        const float fac0 = exp2f(mrun[0] - mn0);
        const float fac1 = exp2f(mrun[1] - mn1);
        mrun[0] = mn0; mrun[1] = mn1;

        uint32_t P[4][4];
        float rs0 = 0.0f, rs1 = 0.0f;
        #pragma unroll
        for (int ks = 0; ks < 4; ++ks) {
            #pragma unroll
            for (int j = 0; j < 2; j++) {
                const int nf = 2 * ks + j;
                const uint32_t p0 = ex2_f16x2(cvt_f16x2(S[nf][0] - mn0, S[nf][1] - mn0));
                const uint32_t p1 = ex2_f16x2(cvt_f16x2(S[nf][2] - mn1, S[nf][3] - mn1));
                P[ks][2 * j]     = p0;
                P[ks][2 * j + 1] = p1;
                rs0 += sum_f16x2(p0);
                rs1 += sum_f16x2(p1);
            }
        }
        rs0 += __shfl_xor_sync(0xffffffffu, rs0, 1);
        rs0 += __shfl_xor_sync(0xffffffffu, rs0, 2);
        rs1 += __shfl_xor_sync(0xffffffffu, rs1, 1);
        rs1 += __shfl_xor_sync(0xffffffffu, rs1, 2);
        lrun[0] = lrun[0] * fac0 + rs0;
        lrun[1] = lrun[1] * fac1 + rs1;

        #pragma unroll
        for (int nf = 0; nf < 16; nf++) {
            O[nf][0] *= fac0; O[nf][1] *= fac0;
            O[nf][2] *= fac1; O[nf][3] *= fac1;
        }

        #pragma unroll
        for (int ks = 0; ks < 4; ++ks) {
            uint32_t vh2[16][2];
            #pragma unroll
            for (int g = 0; g < 8; g++) {
                const uint32_t ro = (uint32_t)(nl + g * 16) * 128
                                  + kh * 16 + ks * 32;
                uint32_t t[4];
                ldsm4(t, kb + 16384 + swz(ro));
                vh2[2*g][0] = t[0]; vh2[2*g][1] = t[1];
                vh2[2*g+1][0] = t[2]; vh2[2*g+1][1] = t[3];
            }
            #pragma unroll
            for (int nf = 0; nf < 16; nf++)
                mma16816(O[nf], P[ks], vh2[nf][0], vh2[nf][1]);
        }
    }

    const float linv0 = 1.0f / lrun[0];
    const float linv1 = 1.0f / lrun[1];
    const int b = bh >> 4, h = bh & 15;
    const int r = qt * 128 + wid * 16 + (lane >> 2);
    #pragma unroll
    for (int nf = 0; nf < 16; nf++) {
        const int c = nf * 8 + (lane & 3) * 2;
        const size_t base = ((size_t)b * SEQ + r) * HID + (size_t)h * 128 + c;
        *(uint32_t*)(Ah_ + base) = hf2pack(O[nf][0] * linv0, O[nf][1] * linv0);
        *(uint32_t*)(Ah_ + base + (size_t)8 * HID) =
            hf2pack(O[nf][2] * linv1, O[nf][3] * linv1);
    }
}

// ============================================================================
// Conversions
// ============================================================================
__global__ __launch_bounds__(256)
void conv_round_h(const float4* __restrict__ in, uint32_t* __restrict__ hi, int n4)
{
    int i = blockIdx.x * blockDim.x + threadIdx.x;
    if (i >= n4) return;
    float4 v = in[i];
    hi[2 * i]     = hf2pack(v.x, v.y);
    hi[2 * i + 1] = hf2pack(v.z, v.w);
}

__global__ __launch_bounds__(256)
void conv_round_h4(const float4* __restrict__ w0, const float4* __restrict__ w1,
                   const float4* __restrict__ w2, const float4* __restrict__ w3,
                   uint32_t* __restrict__ o0, uint32_t* __restrict__ o1,
                   uint32_t* __restrict__ o2, uint32_t* __restrict__ o3, int n4)
{
    int i = blockIdx.x * blockDim.x + threadIdx.x;
    if (i >= n4) return;
    const float4* in = (blockIdx.y == 0) ? w0 : (blockIdx.y == 1) ? w1
                     : (blockIdx.y == 2) ? w2 : w3;
    uint32_t* hi = (blockIdx.y == 0) ? o0 : (blockIdx.y == 1) ? o1
                 : (blockIdx.y == 2) ? o2 : o3;
    float4 v = in[i];
    hi[2 * i]     = hf2pack(v.x, v.y);
    hi[2 * i + 1] = hf2pack(v.z, v.w);
}

// ============================================================================
// kernel_launch
// ============================================================================
extern "C" void kernel_launch(void* const* d_in, const int* in_sizes, int n_in,
                              void* d_out, int out_size)
{
    const float* x  = (const float*)d_in[0];
    const float* Wq = (const float*)d_in[1];
    const float* bq = (const float*)d_in[2];
    const float* Wk = (const float*)d_in[3];
    const float* bk = (const float*)d_in[4];
    const float* Wv = (const float*)d_in[5];
    const float* bv = (const float*)d_in[6];
    const float* Wo = (const float*)d_in[7];
    const float* bo = (const float*)d_in[8];
    float* out = (float*)d_out;

    unsigned char* pool;
    cudaGetSymbolAddress((void**)&pool, g_pool);
    auto hfp = [&](size_t off) { return (__half*)(pool + off); };
    auto u32 = [&](size_t off) { return (uint32_t*)(pool + off); };

    cudaFuncSetAttribute(qkv_mma,    cudaFuncAttributeMaxDynamicSharedMemorySize, SMEM_BYTES);
    cudaFuncSetAttribute(gemm_out,   cudaFuncAttributeMaxDynamicSharedMemorySize, SMEM_BYTES);
    cudaFuncSetAttribute(flash_attn, cudaFuncAttributeMaxDynamicSharedMemorySize, FL_SMEM);

    // 1/sqrt(128) * log2(e): scores come out in log2 domain
    const float scale = 0.08838834764831845f * 1.44269504088896340736f;

    // 1) conversions
    conv_round_h<<<8192, 256>>>((const float4*)x, u32(OFF_XH), 2097152);
    dim3 gW(4096, 4, 1);
    conv_round_h4<<<gW, 256>>>((const float4*)Wq, (const float4*)Wk,
                               (const float4*)Wv, (const float4*)Wo,
                               u32(OFF_WQH), u32(OFF_WKH),
                               u32(OFF_WVH), u32(OFF_WOH), 1048576);

    // 2) fused QKV projections (64x64 warp tiles, 128 threads)
    dim3 gQKV(16, 32, 3);
    qkv_mma<<<gQKV, 128, SMEM_BYTES>>>(
        hfp(OFF_XH),
        hfp(OFF_WQH), hfp(OFF_WKH), hfp(OFF_WVH),
        bq, bk, bv,
        hfp(OFF_QH), hfp(OFF_KH), hfp(OFF_VTH), scale);

    // 3) fused flash attention (proven version)
    dim3 gF(SEQ / 128, BATCH * HEADS, 1);
    flash_attn<<<gF, 256, FL_SMEM>>>(hfp(OFF_QH), hfp(OFF_KH),
                                     hfp(OFF_VTH), hfp(OFF_AH));

    // 4) output projection
    dim3 gO(16, 32, 1);
    gemm_out<<<gO, 128, SMEM_BYTES>>>(hfp(OFF_AH), hfp(OFF_WOH), out, bo);
}